// round 10
// baseline (speedup 1.0000x reference)
#include <cuda_runtime.h>
#include <cuda_bf16.h>
#include <math.h>

#define Bv   64
#define Tv   256
#define Hv   1024
#define Sv   128
#define OBSv 1024
#define ACTv 32
#define NBLK 148
#define NTHR 256
#define KC   128
#define XST  132   // s_x row stride in floats (528B: 16B-aligned, conflict-free)

// ------------------- persistent device scratch (no allocation) -------------
__device__ float g_h[2][Bv * Hv];
__device__ float g_z[Bv * Sv];
__device__ float g_a1[Bv * 512];    // prior L1 activations
__device__ float g_a2[Bv * 1024];   // posterior L1 activations
__device__ unsigned int g_barc;
__device__ volatile unsigned int g_barg;

__device__ __forceinline__ void fma4(float& a, float4 xv, float4 wv) {
    a = fmaf(xv.x, wv.x, a);
    a = fmaf(xv.y, wv.y, a);
    a = fmaf(xv.z, wv.z, a);
    a = fmaf(xv.w, wv.w, a);
}

__device__ __forceinline__ float sigm(float x) { return 1.f / (1.f + expf(-x)); }
__device__ __forceinline__ float sftp(float x) { return (x > 20.f) ? x : log1pf(expf(x)); }

// ------------------- grid-wide sense-reversal barrier ----------------------
// Safe because grid == 148 blocks <= 152 SMs, 1 block/SM resources, all
// co-resident in wave 1. Generation read BEFORE arrival; counter self-resets.
__device__ __forceinline__ void gridbar() {
    __threadfence();
    __syncthreads();
    if (threadIdx.x == 0) {
        unsigned int my = g_barg;
        if (atomicAdd(&g_barc, 1u) == NBLK - 1u) {
            g_barc = 0u;
            __threadfence();
            g_barg = my + 1u;
        } else {
            while (g_barg == my) __nanosleep(64);
        }
    }
    __syncthreads();
}

__device__ __forceinline__ void gru_fin(
    float aR, float aU, float aIN, float aHN, int b, int j, int t, float km,
    const float* __restrict__ hp, float* __restrict__ hc,
    const float* __restrict__ b_ih, const float* __restrict__ b_hh,
    float* __restrict__ o_h)
{
    float hm = __ldcg(&hp[b * Hv + j]) * km;
    float r  = sigm(aR + __ldg(&b_ih[j])        + __ldg(&b_hh[j]));
    float u  = sigm(aU + __ldg(&b_ih[Hv + j])   + __ldg(&b_hh[Hv + j]));
    float n  = tanhf(aIN + __ldg(&b_ih[2*Hv+j]) + r * (aHN + __ldg(&b_hh[2*Hv+j])));
    float hn = (1.f - u) * n + u * hm;
    hc[b * Hv + j] = hn;
    o_h[((size_t)b * Tv + t) * Hv + j] = hn;
}

__global__ void __launch_bounds__(NTHR, 1)
rssm_kernel(const float* __restrict__ obs, const float* __restrict__ action,
            const unsigned char* __restrict__ resets, const float* __restrict__ noise,
            const float* __restrict__ w_ih, const float* __restrict__ w_hh,
            const float* __restrict__ b_ih, const float* __restrict__ b_hh,
            const float* __restrict__ pw1, const float* __restrict__ pb1,
            const float* __restrict__ pw2, const float* __restrict__ pb2,
            const float* __restrict__ qw1, const float* __restrict__ qb1,
            const float* __restrict__ qw2, const float* __restrict__ qb2,
            float* __restrict__ out)
{
    __shared__ __align__(16) float s_x[Bv * XST];   // 33.8 KB
    __shared__ __align__(16) float s_w[24 * KC];    // 12.3 KB
    __shared__ float s_keep[Bv];
    __shared__ float s_ex[2 * Bv];

    const int tid = threadIdx.x, bid = blockIdx.x;
    const int b = tid & 63, slot = tid >> 6;   // 64 batch rows x 4 column-slots

    float* o_pm = out;
    float* o_ps = out + (size_t)1 * Bv * Sv * Tv;
    float* o_qm = out + (size_t)2 * Bv * Sv * Tv;
    float* o_qs = out + (size_t)3 * Bv * Sv * Tv;
    float* o_h  = out + (size_t)4 * Bv * Sv * Tv;
    float* o_z  = o_h + (size_t)Bv * Tv * Hv;

    // init carried state (per launch -> deterministic across graph replays)
    for (int i = bid * NTHR + tid; i < Bv * Hv; i += NBLK * NTHR) g_h[0][i] = 0.f;
    for (int i = bid * NTHR + tid; i < Bv * Sv; i += NBLK * NTHR) g_z[i] = 0.f;
    if (tid < Bv) s_keep[tid] = resets[tid] ? 0.f : 1.f;
    gridbar();

    for (int t = 0; t < Tv; ++t) {
        const float* hp = g_h[t & 1];
        float* hc = g_h[(t + 1) & 1];

        // ================= Phase A: GRU gates + pointwise ==================
        if (bid < 128) {
            const int c0 = bid * 8;
            const int j0 = c0 + 2 * slot, j1 = j0 + 1;
            float aR0=0.f, aU0=0.f, aIN0=0.f, aHN0=0.f;
            float aR1=0.f, aU1=0.f, aIN1=0.f, aHN1=0.f;
            const float* xr = s_x + b * XST;
            const float* w0 = s_w + (2 * slot) * KC;

            // ---- part 1a: x-side, K chunk [0,128): masked z, w_ih ----
            for (int i = tid; i < Bv * KC; i += NTHR) {
                int bb = i >> 7, k = i & 127;
                s_x[bb * XST + k] = __ldcg(&g_z[bb * Sv + k]) * s_keep[bb];
            }
            for (int i = tid; i < 24 * KC; i += NTHR) {
                int r = i >> 7, k = i & 127;
                int g = r >> 3, u = r & 7;
                s_w[r * KC + k] = __ldg(&w_ih[(size_t)(g * Hv + c0 + u) * 160 + k]);
            }
            __syncthreads();
            for (int k = 0; k < KC; k += 4) {
                float4 x4 = *(const float4*)(xr + k);
                fma4(aR0,  x4, *(const float4*)(w0 + k));
                fma4(aR1,  x4, *(const float4*)(w0 + KC + k));
                fma4(aU0,  x4, *(const float4*)(w0 + 8*KC + k));
                fma4(aU1,  x4, *(const float4*)(w0 + 9*KC + k));
                fma4(aIN0, x4, *(const float4*)(w0 + 16*KC + k));
                fma4(aIN1, x4, *(const float4*)(w0 + 17*KC + k));
            }
            __syncthreads();

            // ---- part 1b: x-side, K chunk [128,160): prev_action ----
            for (int i = tid; i < Bv * 32; i += NTHR) {
                int bb = i >> 5, k = i & 31;
                float v = (t == 0) ? 0.f
                        : __ldg(&action[((size_t)bb * Tv + (t - 1)) * ACTv + k]);
                s_x[bb * XST + k] = v;
            }
            for (int i = tid; i < 24 * 32; i += NTHR) {
                int r = i >> 5, k = i & 31;
                int g = r >> 3, u = r & 7;
                s_w[r * KC + k] = __ldg(&w_ih[(size_t)(g * Hv + c0 + u) * 160 + 128 + k]);
            }
            __syncthreads();
            for (int k = 0; k < 32; k += 4) {
                float4 x4 = *(const float4*)(xr + k);
                fma4(aR0,  x4, *(const float4*)(w0 + k));
                fma4(aR1,  x4, *(const float4*)(w0 + KC + k));
                fma4(aU0,  x4, *(const float4*)(w0 + 8*KC + k));
                fma4(aU1,  x4, *(const float4*)(w0 + 9*KC + k));
                fma4(aIN0, x4, *(const float4*)(w0 + 16*KC + k));
                fma4(aIN1, x4, *(const float4*)(w0 + 17*KC + k));
            }
            __syncthreads();

            // ---- part 2: h-side, K=1024 masked h, w_hh ----
            for (int c = 0; c < 8; ++c) {
                const int k0 = c * KC;
                for (int i = tid; i < Bv * KC; i += NTHR) {
                    int bb = i >> 7, k = i & 127;
                    s_x[bb * XST + k] = __ldcg(&hp[bb * Hv + k0 + k]) * s_keep[bb];
                }
                for (int i = tid; i < 24 * KC; i += NTHR) {
                    int r = i >> 7, k = i & 127;
                    int g = r >> 3, u = r & 7;
                    s_w[r * KC + k] = __ldg(&w_hh[(size_t)(g * Hv + c0 + u) * Hv + k0 + k]);
                }
                __syncthreads();
                for (int k = 0; k < KC; k += 4) {
                    float4 x4 = *(const float4*)(xr + k);
                    fma4(aR0,  x4, *(const float4*)(w0 + k));
                    fma4(aR1,  x4, *(const float4*)(w0 + KC + k));
                    fma4(aU0,  x4, *(const float4*)(w0 + 8*KC + k));
                    fma4(aU1,  x4, *(const float4*)(w0 + 9*KC + k));
                    fma4(aHN0, x4, *(const float4*)(w0 + 16*KC + k));
                    fma4(aHN1, x4, *(const float4*)(w0 + 17*KC + k));
                }
                __syncthreads();
            }

            const float km = s_keep[b];
            gru_fin(aR0, aU0, aIN0, aHN0, b, j0, t, km, hp, hc, b_ih, b_hh, o_h);
            gru_fin(aR1, aU1, aIN1, aHN1, b, j1, t, km, hp, hc, b_ih, b_hh, o_h);
        }
        gridbar();

        // ================= Phase B: the two L1 GEMMs =======================
        // B1: posterior L1 (1024 cols, K=2048 = h || obs), blocks 0..146, 7 cols
        if (bid * 7 < 1024) {
            const int c0 = bid * 7;
            const int nc = min(7, 1024 - c0);
            const int l0 = slot, l1 = slot + 4;
            const int e0 = (l0 < nc) ? l0 : 0, e1 = (l1 < nc) ? l1 : 0;
            float a0 = 0.f, a1 = 0.f;
            const float* xr = s_x + b * XST;
            for (int c = 0; c < 16; ++c) {
                const int k0 = c * KC;
                for (int i = tid; i < Bv * KC; i += NTHR) {
                    int bb = i >> 7, k = i & 127, kg = k0 + k;
                    float v = (kg < Hv)
                        ? __ldcg(&hc[bb * Hv + kg])
                        : __ldg(&obs[((size_t)bb * Tv + t) * OBSv + (kg - Hv)]);
                    s_x[bb * XST + k] = v;
                }
                for (int i = tid; i < nc * KC; i += NTHR) {
                    int r = i >> 7, k = i & 127;
                    s_w[r * KC + k] = __ldg(&qw1[(size_t)(c0 + r) * 2048 + k0 + k]);
                }
                __syncthreads();
                for (int k = 0; k < KC; k += 4) {
                    float4 x4 = *(const float4*)(xr + k);
                    fma4(a0, x4, *(const float4*)(s_w + e0 * KC + k));
                    fma4(a1, x4, *(const float4*)(s_w + e1 * KC + k));
                }
                __syncthreads();
            }
            if (l0 < nc) g_a2[b * 1024 + c0 + l0] = fmaxf(a0 + __ldg(&qb1[c0 + l0]), 0.f);
            if (l1 < nc) g_a2[b * 1024 + c0 + l1] = fmaxf(a1 + __ldg(&qb1[c0 + l1]), 0.f);
        }
        // B2: prior L1 (512 cols, K=1024 = h), blocks 0..127, 4 cols
        if (bid < 128) {
            const int c0 = bid * 4;
            const int j = c0 + slot;
            float a0 = 0.f;
            const float* xr = s_x + b * XST;
            const float* wr = s_w + slot * KC;
            for (int c = 0; c < 8; ++c) {
                const int k0 = c * KC;
                for (int i = tid; i < Bv * KC; i += NTHR) {
                    int bb = i >> 7, k = i & 127;
                    s_x[bb * XST + k] = __ldcg(&hc[bb * Hv + k0 + k]);
                }
                for (int i = tid; i < 4 * KC; i += NTHR) {
                    int r = i >> 7, k = i & 127;
                    s_w[r * KC + k] = __ldg(&pw1[(size_t)(c0 + r) * 1024 + k0 + k]);
                }
                __syncthreads();
                for (int k = 0; k < KC; k += 4) {
                    float4 x4 = *(const float4*)(xr + k);
                    fma4(a0, x4, *(const float4*)(wr + k));
                }
                __syncthreads();
            }
            g_a1[b * 512 + j] = fmaxf(a0 + __ldg(&pb1[j]), 0.f);
        }
        gridbar();

        // ================= Phase C: heads (mu/sigma pairs) + z =============
        // blocks 0..63 prior (2 s each), 64..127 posterior (2 s each)
        if (bid < 128) {
            const bool post   = (bid >= 64);
            const int base_s  = (post ? (bid - 64) : bid) * 2;
            const int p       = slot >> 1;     // local s pair 0/1
            const int role    = slot & 1;      // 0 = mu row, 1 = sigma row
            const int s       = base_s + p;
            const float* W2 = post ? qw2 : pw2;
            const float* B2 = post ? qb2 : pb2;
            const float* A  = post ? g_a2 : g_a1;
            const int K     = post ? 1024 : 512;
            float acc = 0.f;
            const float* xr = s_x + b * XST;
            const float* wr = s_w + slot * KC;
            for (int c = 0; c < K / KC; ++c) {
                const int k0 = c * KC;
                for (int i = tid; i < Bv * KC; i += NTHR) {
                    int bb = i >> 7, k = i & 127;
                    s_x[bb * XST + k] = __ldcg(&A[bb * K + k0 + k]);
                }
                for (int i = tid; i < 4 * KC; i += NTHR) {
                    int r = i >> 7, k = i & 127;
                    int pp = r >> 1, rr = r & 1;
                    int rowr = (rr ? Sv : 0) + base_s + pp;
                    s_w[r * KC + k] = __ldg(&W2[(size_t)rowr * K + k0 + k]);
                }
                __syncthreads();
                for (int k = 0; k < KC; k += 4) {
                    float4 x4 = *(const float4*)(xr + k);
                    fma4(acc, x4, *(const float4*)(wr + k));
                }
                __syncthreads();
            }
            const int row = (role ? Sv : 0) + s;
            float v = acc + __ldg(&B2[row]);
            size_t oidx = ((size_t)b * Sv + s) * Tv + t;
            if (role == 0) {
                (post ? o_qm : o_pm)[oidx] = v;          // mu
            } else {
                float sd = sftp(v) + 1e-6f;              // sigma
                (post ? o_qs : o_ps)[oidx] = sd;
                if (post) s_ex[p * Bv + b] = sd;
            }
            __syncthreads();
            if (post && role == 0) {
                float sd = s_ex[p * Bv + b];
                float nz = __ldg(&noise[((size_t)b * Tv + t) * Sv + s]);
                float z = v + sd * nz;                   // rsample
                g_z[b * Sv + s] = z;
                o_z[((size_t)b * Tv + t) * Sv + s] = z;
            }
        }
        gridbar();
    }
}

extern "C" void kernel_launch(void* const* d_in, const int* in_sizes, int n_in,
                              void* d_out, int out_size) {
    (void)in_sizes; (void)n_in; (void)out_size;
    rssm_kernel<<<NBLK, NTHR>>>(
        (const float*)d_in[0],          // obs
        (const float*)d_in[1],          // action
        (const unsigned char*)d_in[2],  // resets (bool)
        (const float*)d_in[3],          // noise
        (const float*)d_in[4],          // w_ih
        (const float*)d_in[5],          // w_hh
        (const float*)d_in[6],          // b_ih
        (const float*)d_in[7],          // b_hh
        (const float*)d_in[8],          // pr_w1
        (const float*)d_in[9],          // pr_b1
        (const float*)d_in[10],         // pr_w2
        (const float*)d_in[11],         // pr_b2
        (const float*)d_in[12],         // po_w1
        (const float*)d_in[13],         // po_b1
        (const float*)d_in[14],         // po_w2
        (const float*)d_in[15],         // po_b2
        (float*)d_out);
}

// round 13
// speedup vs baseline: 3.4649x; 3.4649x over previous
#include <cuda_runtime.h>
#include <math.h>

#define Bv   64
#define Tv   256
#define Hv   1024
#define Sv   128
#define OBSv 1024
#define ACTv 32
#define NBLK 148
#define NTHR 512
#define KC   128
#define XST  132     // s_x row stride (floats)
#define RST  9       // reduction seg stride (padding)

// ---------------- persistent device scratch (no allocation) ----------------
__device__ __align__(16) float g_h[2][Bv * Hv];  // recurrent h (stored pre-masked)
__device__ __align__(16) float g_z[Bv * Sv];     // recurrent z (stored pre-masked)
__device__ __align__(16) float g_a1[Bv * 512];   // prior L1 activations
__device__ __align__(16) float g_a2[Bv * 1024];  // posterior L1 activations
__device__ unsigned int g_barc;
__device__ volatile unsigned int g_barg;

__device__ __forceinline__ void fma4(float& a, float4 xv, const float* wp) {
    float4 wv = *(const float4*)wp;
    a = fmaf(xv.x, wv.x, a);
    a = fmaf(xv.y, wv.y, a);
    a = fmaf(xv.z, wv.z, a);
    a = fmaf(xv.w, wv.w, a);
}
__device__ __forceinline__ float sigm(float x) { return 1.f / (1.f + expf(-x)); }
__device__ __forceinline__ float sftp(float x) { return (x > 20.f) ? x : log1pf(expf(x)); }

// cp.async.cg: 16B global->shared, L2 path (read-only weight data only)
__device__ __forceinline__ void cpacg(float* dst, const float* src) {
    unsigned int d = (unsigned int)__cvta_generic_to_shared(dst);
    asm volatile("cp.async.cg.shared.global [%0], [%1], 16;" :: "r"(d), "l"(src));
}
#define CPCOMMIT() asm volatile("cp.async.commit_group;")
#define CPWAIT1()  asm volatile("cp.async.wait_group 1;")
#define CPWAIT0()  asm volatile("cp.async.wait_group 0;")

// ------------------- grid-wide sense-reversal barrier ----------------------
__device__ __forceinline__ void gridbar() {
    __threadfence();
    __syncthreads();
    if (threadIdx.x == 0) {
        unsigned int my = g_barg;
        if (atomicAdd(&g_barc, 1u) == NBLK - 1u) {
            g_barc = 0u;
            __threadfence();
            g_barg = my + 1u;
        } else {
            while (g_barg == my) __nanosleep(64);
            __threadfence();
        }
    }
    __syncthreads();
}

#define SMEM_FLOATS (2*Bv*XST + 2*21*KC + Bv + 2*Bv)
#define SMEM_BYTES  (SMEM_FLOATS * 4)

__global__ void __launch_bounds__(NTHR, 1)
rssm_kernel(const float* __restrict__ obs, const float* __restrict__ action,
            const unsigned char* __restrict__ resets, const float* __restrict__ noise,
            const float* __restrict__ w_ih, const float* __restrict__ w_hh,
            const float* __restrict__ b_ih, const float* __restrict__ b_hh,
            const float* __restrict__ pw1, const float* __restrict__ pb1,
            const float* __restrict__ pw2, const float* __restrict__ pb2,
            const float* __restrict__ qw1, const float* __restrict__ qb1,
            const float* __restrict__ qw2, const float* __restrict__ qb2,
            float* __restrict__ out)
{
    extern __shared__ __align__(16) float sm[];
    float* s_xa   = sm;                        // 2 bufs x 64 x XST
    float* s_wa   = sm + 2*Bv*XST;             // 2 bufs x 21 x KC
    float* s_keep = s_wa + 2*21*KC;            // 64
    float* s_ex   = s_keep + Bv;               // 128 (sigma exchange)
    float* s_red  = s_xa;                      // reduction scratch (aliases x bufs)

    const int tid = threadIdx.x, bid = blockIdx.x;
    const int b = tid & 63, seg = tid >> 6;    // 64 batch lanes x 8 K-segments
    const int xb0 = tid >> 5;                  // 128-wide staging: row base
    const int xq  = (tid & 31) * 4;            // 128-wide staging: col
    const int ab  = tid >> 3;                  // 32-wide staging row
    const int aq  = (tid & 7) * 4;             // 32-wide staging col

    float* o_pm = out;
    float* o_ps = out + (size_t)1 * Bv * Sv * Tv;
    float* o_qm = out + (size_t)2 * Bv * Sv * Tv;
    float* o_qs = out + (size_t)3 * Bv * Sv * Tv;
    float* o_h  = out + (size_t)4 * Bv * Sv * Tv;
    float* o_z  = o_h + (size_t)Bv * Tv * Hv;

    for (int i = bid * NTHR + tid; i < Bv * Hv; i += NBLK * NTHR) g_h[0][i] = 0.f;
    for (int i = bid * NTHR + tid; i < Bv * Sv; i += NBLK * NTHR) g_z[i] = 0.f;
    if (tid < Bv) s_keep[tid] = resets[tid] ? 0.f : 1.f;
    gridbar();

    float4 xs[4];

    for (int t = 0; t < Tv; ++t) {
        const float* hp = g_h[t & 1];
        float* hc = g_h[(t + 1) & 1];

        // ============ Phase A: GRU gate GEMM (split-K) + pointwise =========
        if (bid < 147) {
            const int c0 = bid * 7;
            float aR[7], aU[7], aNX[7], aNH[7];
            #pragma unroll
            for (int u = 0; u < 7; ++u) { aR[u]=0.f; aU[u]=0.f; aNX[u]=0.f; aNH[u]=0.f; }

            // chunks: 0 = z(128), 1 = prev_action(32), 2..9 = h(8x128)
            auto ldxA = [&](int ct) {
                if (ct == 0) {
                    #pragma unroll
                    for (int j = 0; j < 4; ++j)
                        xs[j] = __ldcg((const float4*)(g_z + (xb0 + 16*j) * Sv + xq));
                } else if (ct == 1) {
                    if (t > 0) xs[0] = __ldcg((const float4*)(action + ((size_t)ab * Tv + (t-1)) * ACTv + aq));
                    else       xs[0] = make_float4(0.f, 0.f, 0.f, 0.f);
                } else {
                    #pragma unroll
                    for (int j = 0; j < 4; ++j)
                        xs[j] = __ldcg((const float4*)(hp + (size_t)(xb0 + 16*j) * Hv + (ct-2) * KC + xq));
                }
            };
            auto stsA = [&](int ct, int buf) {
                float* sx = s_xa + buf * Bv * XST;
                if (ct == 1) *(float4*)(sx + ab * XST + aq) = xs[0];
                else {
                    #pragma unroll
                    for (int j = 0; j < 4; ++j)
                        *(float4*)(sx + (xb0 + 16*j) * XST + xq) = xs[j];
                }
            };
            auto cpwA = [&](int ct, int buf) {
                float* sw = s_wa + buf * 21 * KC;
                if (ct == 1) {
                    for (int i = tid; i < 21 * 8; i += NTHR) {
                        int r = i >> 3, q = (i & 7) * 4;
                        int g = r / 7, uu = r - g * 7;
                        int grow = g * Hv + min(c0 + uu, Hv - 1);
                        cpacg(sw + r * KC + q, w_ih + (size_t)grow * 160 + 128 + q);
                    }
                } else {
                    for (int i = tid; i < 21 * 32; i += NTHR) {
                        int r = i >> 5, q = (i & 31) * 4;
                        int g = r / 7, uu = r - g * 7;
                        int grow = g * Hv + min(c0 + uu, Hv - 1);
                        const float* src = (ct == 0)
                            ? w_ih + (size_t)grow * 160 + q
                            : w_hh + (size_t)grow * Hv + (ct-2) * KC + q;
                        cpacg(sw + r * KC + q, src);
                    }
                }
            };

            ldxA(0); stsA(0, 0); cpwA(0, 0); CPCOMMIT();
            for (int ct = 0; ct < 10; ++ct) {
                const int buf = ct & 1;
                if (ct + 1 < 10) { ldxA(ct + 1); cpwA(ct + 1, buf ^ 1); CPCOMMIT(); CPWAIT1(); }
                else CPWAIT0();
                __syncthreads();
                const float* sw = s_wa + buf * 21 * KC;
                const float* xr = s_xa + buf * Bv * XST + b * XST;
                if (ct == 1) {
                    const int kb = seg * 4;
                    float4 x4 = *(const float4*)(xr + kb);
                    #pragma unroll
                    for (int u = 0; u < 7; ++u) {
                        fma4(aR[u],  x4, sw + u*KC + kb);
                        fma4(aU[u],  x4, sw + (7+u)*KC + kb);
                        fma4(aNX[u], x4, sw + (14+u)*KC + kb);
                    }
                } else if (ct == 0) {
                    const int kb = seg * 16;
                    #pragma unroll
                    for (int kk = 0; kk < 16; kk += 4) {
                        float4 x4 = *(const float4*)(xr + kb + kk);
                        #pragma unroll
                        for (int u = 0; u < 7; ++u) {
                            fma4(aR[u],  x4, sw + u*KC + kb + kk);
                            fma4(aU[u],  x4, sw + (7+u)*KC + kb + kk);
                            fma4(aNX[u], x4, sw + (14+u)*KC + kb + kk);
                        }
                    }
                } else {
                    const int kb = seg * 16;
                    #pragma unroll
                    for (int kk = 0; kk < 16; kk += 4) {
                        float4 x4 = *(const float4*)(xr + kb + kk);
                        #pragma unroll
                        for (int u = 0; u < 7; ++u) {
                            fma4(aR[u],  x4, sw + u*KC + kb + kk);
                            fma4(aU[u],  x4, sw + (7+u)*KC + kb + kk);
                            fma4(aNH[u], x4, sw + (14+u)*KC + kb + kk);
                        }
                    }
                }
                __syncthreads();
                if (ct + 1 < 10) stsA(ct + 1, buf ^ 1);
            }

            #pragma unroll
            for (int u = 0; u < 7; ++u) {
                s_red[((u*4+0)*64 + b)*RST + seg] = aR[u];
                s_red[((u*4+1)*64 + b)*RST + seg] = aU[u];
                s_red[((u*4+2)*64 + b)*RST + seg] = aNX[u];
                s_red[((u*4+3)*64 + b)*RST + seg] = aNH[u];
            }
            __syncthreads();
            if (tid < 448) {
                const int u = tid >> 6, bi = tid & 63;
                const int j = c0 + u;
                if (j < Hv) {
                    float sR = 0.f, sU = 0.f, sX = 0.f, sH = 0.f;
                    #pragma unroll
                    for (int s2 = 0; s2 < 8; ++s2) {
                        sR += s_red[((u*4+0)*64 + bi)*RST + s2];
                        sU += s_red[((u*4+1)*64 + bi)*RST + s2];
                        sX += s_red[((u*4+2)*64 + bi)*RST + s2];
                        sH += s_red[((u*4+3)*64 + bi)*RST + s2];
                    }
                    const float km = s_keep[bi];
                    const float hm = __ldcg(&hp[bi * Hv + j]);     // pre-masked
                    float r  = sigm(sR + __ldg(&b_ih[j])       + __ldg(&b_hh[j]));
                    float uu = sigm(sU + __ldg(&b_ih[Hv+j])    + __ldg(&b_hh[Hv+j]));
                    float n  = tanhf(sX + __ldg(&b_ih[2*Hv+j]) + r * (sH + __ldg(&b_hh[2*Hv+j])));
                    float hn = (1.f - uu) * n + uu * hm;
                    hc[bi * Hv + j] = hn * km;                      // mask folded into store
                    o_h[((size_t)bi * Tv + t) * Hv + j] = hn;
                }
            }
        }
        gridbar();

        // ====== Phase B: posterior L1 (7 cols, K=2048) + fused prior L1 ====
        if (bid < 147) {
            const int c0q = bid * 7;
            const int c0p = bid * 4;
            const bool hasP = (bid < 128);
            float aQ[7], aP[4];
            #pragma unroll
            for (int r = 0; r < 7; ++r) aQ[r] = 0.f;
            #pragma unroll
            for (int r = 0; r < 4; ++r) aP[r] = 0.f;

            auto ldxB = [&](int ct) {
                if (ct < 8) {
                    #pragma unroll
                    for (int j = 0; j < 4; ++j)
                        xs[j] = __ldcg((const float4*)(hc + (size_t)(xb0 + 16*j) * Hv + ct * KC + xq));
                } else {
                    #pragma unroll
                    for (int j = 0; j < 4; ++j)
                        xs[j] = __ldcg((const float4*)(obs + ((size_t)(xb0 + 16*j) * Tv + t) * OBSv + (ct-8) * KC + xq));
                }
            };
            auto stsX = [&](int buf) {
                float* sx = s_xa + buf * Bv * XST;
                #pragma unroll
                for (int j = 0; j < 4; ++j)
                    *(float4*)(sx + (xb0 + 16*j) * XST + xq) = xs[j];
            };
            auto cpwB = [&](int ct, int buf) {
                float* sw = s_wa + buf * 21 * KC;
                for (int i = tid; i < 11 * 32; i += NTHR) {
                    int r = i >> 5, q = (i & 31) * 4;
                    if (r < 7)
                        cpacg(sw + r * KC + q, qw1 + (size_t)min(c0q + r, 1023) * 2048 + ct * KC + q);
                    else if (hasP && ct < 8)
                        cpacg(sw + r * KC + q, pw1 + (size_t)(c0p + r - 7) * Hv + ct * KC + q);
                }
            };

            ldxB(0); stsX(0); cpwB(0, 0); CPCOMMIT();
            for (int ct = 0; ct < 16; ++ct) {
                const int buf = ct & 1;
                if (ct + 1 < 16) { ldxB(ct + 1); cpwB(ct + 1, buf ^ 1); CPCOMMIT(); CPWAIT1(); }
                else CPWAIT0();
                __syncthreads();
                const float* sw = s_wa + buf * 21 * KC;
                const float* xr = s_xa + buf * Bv * XST + b * XST;
                const int kb = seg * 16;
                if (hasP && ct < 8) {
                    #pragma unroll
                    for (int kk = 0; kk < 16; kk += 4) {
                        float4 x4 = *(const float4*)(xr + kb + kk);
                        #pragma unroll
                        for (int r = 0; r < 7; ++r) fma4(aQ[r], x4, sw + r*KC + kb + kk);
                        #pragma unroll
                        for (int r = 0; r < 4; ++r) fma4(aP[r], x4, sw + (7+r)*KC + kb + kk);
                    }
                } else {
                    #pragma unroll
                    for (int kk = 0; kk < 16; kk += 4) {
                        float4 x4 = *(const float4*)(xr + kb + kk);
                        #pragma unroll
                        for (int r = 0; r < 7; ++r) fma4(aQ[r], x4, sw + r*KC + kb + kk);
                    }
                }
                __syncthreads();
                if (ct + 1 < 16) stsX(buf ^ 1);
            }

            #pragma unroll
            for (int r = 0; r < 7; ++r) s_red[(r*64 + b)*RST + seg] = aQ[r];
            #pragma unroll
            for (int r = 0; r < 4; ++r) s_red[((7+r)*64 + b)*RST + seg] = aP[r];
            __syncthreads();
            // FIX (round 12 bug): 11 rows x 64 lanes = 704 > NTHR=512.
            // Loop over row-groups so rows 8..10 (prior L1 cols c0p+1..c0p+3)
            // actually get reduced and written.
            {
                const int bi = tid & 63;
                for (int r = tid >> 6; r < 11; r += 8) {
                    float sum = 0.f;
                    #pragma unroll
                    for (int s2 = 0; s2 < 8; ++s2) sum += s_red[(r*64 + bi)*RST + s2];
                    if (r < 7) {
                        int col = c0q + r;
                        if (col < 1024) g_a2[bi * 1024 + col] = fmaxf(sum + __ldg(&qb1[col]), 0.f);
                    } else if (hasP) {
                        int col = c0p + (r - 7);
                        g_a1[bi * 512 + col] = fmaxf(sum + __ldg(&pb1[col]), 0.f);
                    }
                }
            }
        }
        gridbar();

        // ====== Phase C: heads. blocks 0..31 prior, 32..95 posterior =======
        {
            const bool isPr = (bid < 32);
            const bool isPo = (bid >= 32 && bid < 96);
            if (isPr || isPo) {
                const int NR  = isPr ? 8 : 4;
                const int NCH = isPr ? 4 : 8;
                const int s0  = isPr ? bid * 4 : (bid - 32) * 2;
                const int Kc  = isPr ? 512 : 1024;
                const float* W2 = isPr ? pw2 : qw2;
                const float* B2 = isPr ? pb2 : qb2;
                const float* Ain = isPr ? g_a1 : g_a2;
                float aC[8];
                #pragma unroll
                for (int r = 0; r < 8; ++r) aC[r] = 0.f;

                auto ldxC = [&](int ct) {
                    #pragma unroll
                    for (int j = 0; j < 4; ++j)
                        xs[j] = __ldcg((const float4*)(Ain + (size_t)(xb0 + 16*j) * Kc + ct * KC + xq));
                };
                auto stsX = [&](int buf) {
                    float* sx = s_xa + buf * Bv * XST;
                    #pragma unroll
                    for (int j = 0; j < 4; ++j)
                        *(float4*)(sx + (xb0 + 16*j) * XST + xq) = xs[j];
                };
                auto cpwC = [&](int ct, int buf) {
                    float* sw = s_wa + buf * 21 * KC;
                    for (int i = tid; i < NR * 32; i += NTHR) {
                        int r = i >> 5, q = (i & 31) * 4;
                        int grow = (r & 1) * Sv + s0 + (r >> 1);
                        cpacg(sw + r * KC + q, W2 + (size_t)grow * Kc + ct * KC + q);
                    }
                };

                ldxC(0); stsX(0); cpwC(0, 0); CPCOMMIT();
                for (int ct = 0; ct < NCH; ++ct) {
                    const int buf = ct & 1;
                    if (ct + 1 < NCH) { ldxC(ct + 1); cpwC(ct + 1, buf ^ 1); CPCOMMIT(); CPWAIT1(); }
                    else CPWAIT0();
                    __syncthreads();
                    const float* sw = s_wa + buf * 21 * KC;
                    const float* xr = s_xa + buf * Bv * XST + b * XST;
                    const int kb = seg * 16;
                    if (isPr) {
                        #pragma unroll
                        for (int kk = 0; kk < 16; kk += 4) {
                            float4 x4 = *(const float4*)(xr + kb + kk);
                            #pragma unroll
                            for (int r = 0; r < 8; ++r) fma4(aC[r], x4, sw + r*KC + kb + kk);
                        }
                    } else {
                        #pragma unroll
                        for (int kk = 0; kk < 16; kk += 4) {
                            float4 x4 = *(const float4*)(xr + kb + kk);
                            #pragma unroll
                            for (int r = 0; r < 4; ++r) fma4(aC[r], x4, sw + r*KC + kb + kk);
                        }
                    }
                    __syncthreads();
                    if (ct + 1 < NCH) stsX(buf ^ 1);
                }

                #pragma unroll
                for (int r = 0; r < 8; ++r)
                    if (r < NR) s_red[(r*64 + b)*RST + seg] = aC[r];
                __syncthreads();

                float v = 0.f; int rr = 0, bi = 0, s = 0, role = 0;
                const bool fin = (tid < NR * 64);
                if (fin) {
                    rr = tid >> 6; bi = tid & 63;
                    role = rr & 1; s = s0 + (rr >> 1);
                    float sum = 0.f;
                    #pragma unroll
                    for (int s2 = 0; s2 < 8; ++s2) sum += s_red[(rr*64 + bi)*RST + s2];
                    v = sum + __ldg(&B2[role * Sv + s]);
                    const size_t oidx = ((size_t)bi * Sv + s) * Tv + t;
                    if (isPr) {
                        if (role == 0) o_pm[oidx] = v;
                        else           o_ps[oidx] = sftp(v) + 1e-6f;
                    } else {
                        if (role == 1) {
                            float sd = sftp(v) + 1e-6f;
                            o_qs[oidx] = sd;
                            s_ex[(rr >> 1) * 64 + bi] = sd;
                        }
                    }
                }
                __syncthreads();
                if (isPo && fin && role == 0) {
                    float sd = s_ex[(rr >> 1) * 64 + bi];
                    float nz = __ldg(&noise[((size_t)bi * Tv + t) * Sv + s]);
                    float z  = v + sd * nz;                        // rsample
                    g_z[bi * Sv + s] = z * s_keep[bi];             // mask folded in
                    o_z[((size_t)bi * Tv + t) * Sv + s] = z;
                    o_qm[((size_t)bi * Sv + s) * Tv + t] = v;
                }
            }
        }
        gridbar();
    }
}

extern "C" void kernel_launch(void* const* d_in, const int* in_sizes, int n_in,
                              void* d_out, int out_size) {
    (void)in_sizes; (void)n_in; (void)out_size;
    cudaFuncSetAttribute(rssm_kernel, cudaFuncAttributeMaxDynamicSharedMemorySize, SMEM_BYTES);
    rssm_kernel<<<NBLK, NTHR, SMEM_BYTES>>>(
        (const float*)d_in[0],          // obs
        (const float*)d_in[1],          // action
        (const unsigned char*)d_in[2],  // resets
        (const float*)d_in[3],          // noise
        (const float*)d_in[4],          // w_ih
        (const float*)d_in[5],          // w_hh
        (const float*)d_in[6],          // b_ih
        (const float*)d_in[7],          // b_hh
        (const float*)d_in[8],          // pr_w1
        (const float*)d_in[9],          // pr_b1
        (const float*)d_in[10],         // pr_w2
        (const float*)d_in[11],         // pr_b2
        (const float*)d_in[12],         // po_w1
        (const float*)d_in[13],         // po_b1
        (const float*)d_in[14],         // po_w2
        (const float*)d_in[15],         // po_b2
        (float*)d_out);
}

// round 14
// speedup vs baseline: 3.4742x; 1.0027x over previous
#include <cuda_runtime.h>
#include <math.h>

#define Bv   64
#define Tv   256
#define Hv   1024
#define Sv   128
#define OBSv 1024
#define ACTv 32
#define NBLK 148
#define NTHR 512
#define KC   128
#define XST  132     // s_x row stride (floats)
#define RST  9       // reduction seg stride (padding)

// ---------------- persistent device scratch (no allocation) ----------------
__device__ __align__(16) float g_h[2][Bv * Hv];  // recurrent h (stored pre-masked)
__device__ __align__(16) float g_z[Bv * Sv];     // recurrent z (stored pre-masked)
__device__ __align__(16) float g_a1[Bv * 512];   // prior L1 activations
__device__ __align__(16) float g_a2[Bv * 1024];  // posterior L1 activations
__device__ unsigned int g_barc;
__device__ volatile unsigned int g_barg;

__device__ __forceinline__ void fma4(float& a, float4 xv, const float* wp) {
    float4 wv = *(const float4*)wp;
    a = fmaf(xv.x, wv.x, a);
    a = fmaf(xv.y, wv.y, a);
    a = fmaf(xv.z, wv.z, a);
    a = fmaf(xv.w, wv.w, a);
}
__device__ __forceinline__ float sigm(float x) { return 1.f / (1.f + expf(-x)); }
__device__ __forceinline__ float sftp(float x) { return (x > 20.f) ? x : log1pf(expf(x)); }

// cp.async.cg: 16B global->shared, L2 path (read-only weight data only)
__device__ __forceinline__ void cpacg(float* dst, const float* src) {
    unsigned int d = (unsigned int)__cvta_generic_to_shared(dst);
    asm volatile("cp.async.cg.shared.global [%0], [%1], 16;" :: "r"(d), "l"(src));
}
#define CPCOMMIT() asm volatile("cp.async.commit_group;")
#define CPWAIT1()  asm volatile("cp.async.wait_group 1;")
#define CPWAIT0()  asm volatile("cp.async.wait_group 0;")

// ------------------- grid-wide sense-reversal barrier ----------------------
__device__ __forceinline__ void gridbar() {
    __threadfence();
    __syncthreads();
    if (threadIdx.x == 0) {
        unsigned int my = g_barg;
        if (atomicAdd(&g_barc, 1u) == NBLK - 1u) {
            g_barc = 0u;
            __threadfence();
            g_barg = my + 1u;
        } else {
            while (g_barg == my) __nanosleep(64);
            __threadfence();
        }
    }
    __syncthreads();
}

#define SMEM_FLOATS (2*Bv*XST + 2*21*KC + Bv + 2*Bv)
#define SMEM_BYTES  (SMEM_FLOATS * 4)

__global__ void __launch_bounds__(NTHR, 1)
rssm_kernel(const float* __restrict__ obs, const float* __restrict__ action,
            const unsigned char* __restrict__ resets, const float* __restrict__ noise,
            const float* __restrict__ w_ih, const float* __restrict__ w_hh,
            const float* __restrict__ b_ih, const float* __restrict__ b_hh,
            const float* __restrict__ pw1, const float* __restrict__ pb1,
            const float* __restrict__ pw2, const float* __restrict__ pb2,
            const float* __restrict__ qw1, const float* __restrict__ qb1,
            const float* __restrict__ qw2, const float* __restrict__ qb2,
            float* __restrict__ out)
{
    extern __shared__ __align__(16) float sm[];
    float* s_xa   = sm;                        // 2 bufs x 64 x XST
    float* s_wa   = sm + 2*Bv*XST;             // 2 bufs x 21 x KC
    float* s_keep = s_wa + 2*21*KC;            // 64
    float* s_ex   = s_keep + Bv;               // 128 (sigma exchange)
    float* s_red  = s_xa;                      // reduction scratch (aliases x bufs)

    const int tid = threadIdx.x, bid = blockIdx.x;
    const int b = tid & 63, seg = tid >> 6;    // 64 batch lanes x 8 K-segments
    const int xb0 = tid >> 5;                  // 128-wide staging: row base
    const int xq  = (tid & 31) * 4;            // 128-wide staging: col
    const int ab  = tid >> 3;                  // 32-wide staging row
    const int aq  = (tid & 7) * 4;             // 32-wide staging col

    float* o_pm = out;
    float* o_ps = out + (size_t)1 * Bv * Sv * Tv;
    float* o_qm = out + (size_t)2 * Bv * Sv * Tv;
    float* o_qs = out + (size_t)3 * Bv * Sv * Tv;
    float* o_h  = out + (size_t)4 * Bv * Sv * Tv;
    float* o_z  = o_h + (size_t)Bv * Tv * Hv;

    for (int i = bid * NTHR + tid; i < Bv * Hv; i += NBLK * NTHR) g_h[0][i] = 0.f;
    for (int i = bid * NTHR + tid; i < Bv * Sv; i += NBLK * NTHR) g_z[i] = 0.f;
    if (tid < Bv) s_keep[tid] = resets[tid] ? 0.f : 1.f;
    gridbar();

    float4 xs[4];

    for (int t = 0; t < Tv; ++t) {
        const float* hp = g_h[t & 1];
        float* hc = g_h[(t + 1) & 1];

        // ============ Phase A: GRU gate GEMM (split-K) + pointwise =========
        if (bid < 147) {
            const int c0 = bid * 7;
            float aR[7], aU[7], aNX[7], aNH[7];
            #pragma unroll
            for (int u = 0; u < 7; ++u) { aR[u]=0.f; aU[u]=0.f; aNX[u]=0.f; aNH[u]=0.f; }

            // chunks: 0 = z(128), 1 = prev_action(32), 2..9 = h(8x128)
            auto ldxA = [&](int ct) {
                if (ct == 0) {
                    #pragma unroll
                    for (int j = 0; j < 4; ++j)
                        xs[j] = __ldcg((const float4*)(g_z + (xb0 + 16*j) * Sv + xq));
                } else if (ct == 1) {
                    if (t > 0) xs[0] = __ldcg((const float4*)(action + ((size_t)ab * Tv + (t-1)) * ACTv + aq));
                    else       xs[0] = make_float4(0.f, 0.f, 0.f, 0.f);
                } else {
                    #pragma unroll
                    for (int j = 0; j < 4; ++j)
                        xs[j] = __ldcg((const float4*)(hp + (size_t)(xb0 + 16*j) * Hv + (ct-2) * KC + xq));
                }
            };
            auto stsA = [&](int ct, int buf) {
                float* sx = s_xa + buf * Bv * XST;
                if (ct == 1) *(float4*)(sx + ab * XST + aq) = xs[0];
                else {
                    #pragma unroll
                    for (int j = 0; j < 4; ++j)
                        *(float4*)(sx + (xb0 + 16*j) * XST + xq) = xs[j];
                }
            };
            auto cpwA = [&](int ct, int buf) {
                float* sw = s_wa + buf * 21 * KC;
                if (ct == 1) {
                    for (int i = tid; i < 21 * 8; i += NTHR) {
                        int r = i >> 3, q = (i & 7) * 4;
                        int g = r / 7, uu = r - g * 7;
                        int grow = g * Hv + min(c0 + uu, Hv - 1);
                        cpacg(sw + r * KC + q, w_ih + (size_t)grow * 160 + 128 + q);
                    }
                } else {
                    for (int i = tid; i < 21 * 32; i += NTHR) {
                        int r = i >> 5, q = (i & 31) * 4;
                        int g = r / 7, uu = r - g * 7;
                        int grow = g * Hv + min(c0 + uu, Hv - 1);
                        const float* src = (ct == 0)
                            ? w_ih + (size_t)grow * 160 + q
                            : w_hh + (size_t)grow * Hv + (ct-2) * KC + q;
                        cpacg(sw + r * KC + q, src);
                    }
                }
            };

            ldxA(0); stsA(0, 0); cpwA(0, 0); CPCOMMIT();
            for (int ct = 0; ct < 10; ++ct) {
                const int buf = ct & 1;
                if (ct + 1 < 10) { ldxA(ct + 1); cpwA(ct + 1, buf ^ 1); CPCOMMIT(); CPWAIT1(); }
                else CPWAIT0();
                __syncthreads();
                const float* sw = s_wa + buf * 21 * KC;
                const float* xr = s_xa + buf * Bv * XST + b * XST;
                if (ct == 1) {
                    const int kb = seg * 4;
                    float4 x4 = *(const float4*)(xr + kb);
                    #pragma unroll
                    for (int u = 0; u < 7; ++u) {
                        fma4(aR[u],  x4, sw + u*KC + kb);
                        fma4(aU[u],  x4, sw + (7+u)*KC + kb);
                        fma4(aNX[u], x4, sw + (14+u)*KC + kb);
                    }
                } else if (ct == 0) {
                    const int kb = seg * 16;
                    #pragma unroll
                    for (int kk = 0; kk < 16; kk += 4) {
                        float4 x4 = *(const float4*)(xr + kb + kk);
                        #pragma unroll
                        for (int u = 0; u < 7; ++u) {
                            fma4(aR[u],  x4, sw + u*KC + kb + kk);
                            fma4(aU[u],  x4, sw + (7+u)*KC + kb + kk);
                            fma4(aNX[u], x4, sw + (14+u)*KC + kb + kk);
                        }
                    }
                } else {
                    const int kb = seg * 16;
                    #pragma unroll
                    for (int kk = 0; kk < 16; kk += 4) {
                        float4 x4 = *(const float4*)(xr + kb + kk);
                        #pragma unroll
                        for (int u = 0; u < 7; ++u) {
                            fma4(aR[u],  x4, sw + u*KC + kb + kk);
                            fma4(aU[u],  x4, sw + (7+u)*KC + kb + kk);
                            fma4(aNH[u], x4, sw + (14+u)*KC + kb + kk);
                        }
                    }
                }
                __syncthreads();
                if (ct + 1 < 10) stsA(ct + 1, buf ^ 1);
            }

            #pragma unroll
            for (int u = 0; u < 7; ++u) {
                s_red[((u*4+0)*64 + b)*RST + seg] = aR[u];
                s_red[((u*4+1)*64 + b)*RST + seg] = aU[u];
                s_red[((u*4+2)*64 + b)*RST + seg] = aNX[u];
                s_red[((u*4+3)*64 + b)*RST + seg] = aNH[u];
            }
            __syncthreads();
            if (tid < 448) {
                const int u = tid >> 6, bi = tid & 63;
                const int j = c0 + u;
                if (j < Hv) {
                    float sR = 0.f, sU = 0.f, sX = 0.f, sH = 0.f;
                    #pragma unroll
                    for (int s2 = 0; s2 < 8; ++s2) {
                        sR += s_red[((u*4+0)*64 + bi)*RST + s2];
                        sU += s_red[((u*4+1)*64 + bi)*RST + s2];
                        sX += s_red[((u*4+2)*64 + bi)*RST + s2];
                        sH += s_red[((u*4+3)*64 + bi)*RST + s2];
                    }
                    const float km = s_keep[bi];
                    const float hm = __ldcg(&hp[bi * Hv + j]);     // pre-masked
                    float r  = sigm(sR + __ldg(&b_ih[j])       + __ldg(&b_hh[j]));
                    float uu = sigm(sU + __ldg(&b_ih[Hv+j])    + __ldg(&b_hh[Hv+j]));
                    float n  = tanhf(sX + __ldg(&b_ih[2*Hv+j]) + r * (sH + __ldg(&b_hh[2*Hv+j])));
                    float hn = (1.f - uu) * n + uu * hm;
                    hc[bi * Hv + j] = hn * km;                      // mask folded into store
                    o_h[((size_t)bi * Tv + t) * Hv + j] = hn;
                }
            }
        }
        gridbar();

        // ====== Phase B: posterior L1 (7 cols, K=2048) + fused prior L1 ====
        if (bid < 147) {
            const int c0q = bid * 7;
            const int c0p = bid * 4;
            const bool hasP = (bid < 128);
            float aQ[7], aP[4];
            #pragma unroll
            for (int r = 0; r < 7; ++r) aQ[r] = 0.f;
            #pragma unroll
            for (int r = 0; r < 4; ++r) aP[r] = 0.f;

            auto ldxB = [&](int ct) {
                if (ct < 8) {
                    #pragma unroll
                    for (int j = 0; j < 4; ++j)
                        xs[j] = __ldcg((const float4*)(hc + (size_t)(xb0 + 16*j) * Hv + ct * KC + xq));
                } else {
                    #pragma unroll
                    for (int j = 0; j < 4; ++j)
                        xs[j] = __ldcg((const float4*)(obs + ((size_t)(xb0 + 16*j) * Tv + t) * OBSv + (ct-8) * KC + xq));
                }
            };
            auto stsX = [&](int buf) {
                float* sx = s_xa + buf * Bv * XST;
                #pragma unroll
                for (int j = 0; j < 4; ++j)
                    *(float4*)(sx + (xb0 + 16*j) * XST + xq) = xs[j];
            };
            auto cpwB = [&](int ct, int buf) {
                float* sw = s_wa + buf * 21 * KC;
                for (int i = tid; i < 11 * 32; i += NTHR) {
                    int r = i >> 5, q = (i & 31) * 4;
                    if (r < 7)
                        cpacg(sw + r * KC + q, qw1 + (size_t)min(c0q + r, 1023) * 2048 + ct * KC + q);
                    else if (hasP && ct < 8)
                        cpacg(sw + r * KC + q, pw1 + (size_t)(c0p + r - 7) * Hv + ct * KC + q);
                }
            };

            ldxB(0); stsX(0); cpwB(0, 0); CPCOMMIT();
            for (int ct = 0; ct < 16; ++ct) {
                const int buf = ct & 1;
                if (ct + 1 < 16) { ldxB(ct + 1); cpwB(ct + 1, buf ^ 1); CPCOMMIT(); CPWAIT1(); }
                else CPWAIT0();
                __syncthreads();
                const float* sw = s_wa + buf * 21 * KC;
                const float* xr = s_xa + buf * Bv * XST + b * XST;
                const int kb = seg * 16;
                if (hasP && ct < 8) {
                    #pragma unroll
                    for (int kk = 0; kk < 16; kk += 4) {
                        float4 x4 = *(const float4*)(xr + kb + kk);
                        #pragma unroll
                        for (int r = 0; r < 7; ++r) fma4(aQ[r], x4, sw + r*KC + kb + kk);
                        #pragma unroll
                        for (int r = 0; r < 4; ++r) fma4(aP[r], x4, sw + (7+r)*KC + kb + kk);
                    }
                } else {
                    #pragma unroll
                    for (int kk = 0; kk < 16; kk += 4) {
                        float4 x4 = *(const float4*)(xr + kb + kk);
                        #pragma unroll
                        for (int r = 0; r < 7; ++r) fma4(aQ[r], x4, sw + r*KC + kb + kk);
                    }
                }
                __syncthreads();
                if (ct + 1 < 16) stsX(buf ^ 1);
            }

            #pragma unroll
            for (int r = 0; r < 7; ++r) s_red[(r*64 + b)*RST + seg] = aQ[r];
            #pragma unroll
            for (int r = 0; r < 4; ++r) s_red[((7+r)*64 + b)*RST + seg] = aP[r];
            __syncthreads();
            // FIX (round 12 bug): 11 rows x 64 lanes = 704 > NTHR=512.
            // Loop over row-groups so rows 8..10 (prior L1 cols c0p+1..c0p+3)
            // actually get reduced and written.
            {
                const int bi = tid & 63;
                for (int r = tid >> 6; r < 11; r += 8) {
                    float sum = 0.f;
                    #pragma unroll
                    for (int s2 = 0; s2 < 8; ++s2) sum += s_red[(r*64 + bi)*RST + s2];
                    if (r < 7) {
                        int col = c0q + r;
                        if (col < 1024) g_a2[bi * 1024 + col] = fmaxf(sum + __ldg(&qb1[col]), 0.f);
                    } else if (hasP) {
                        int col = c0p + (r - 7);
                        g_a1[bi * 512 + col] = fmaxf(sum + __ldg(&pb1[col]), 0.f);
                    }
                }
            }
        }
        gridbar();

        // ====== Phase C: heads. blocks 0..31 prior, 32..95 posterior =======
        {
            const bool isPr = (bid < 32);
            const bool isPo = (bid >= 32 && bid < 96);
            if (isPr || isPo) {
                const int NR  = isPr ? 8 : 4;
                const int NCH = isPr ? 4 : 8;
                const int s0  = isPr ? bid * 4 : (bid - 32) * 2;
                const int Kc  = isPr ? 512 : 1024;
                const float* W2 = isPr ? pw2 : qw2;
                const float* B2 = isPr ? pb2 : qb2;
                const float* Ain = isPr ? g_a1 : g_a2;
                float aC[8];
                #pragma unroll
                for (int r = 0; r < 8; ++r) aC[r] = 0.f;

                auto ldxC = [&](int ct) {
                    #pragma unroll
                    for (int j = 0; j < 4; ++j)
                        xs[j] = __ldcg((const float4*)(Ain + (size_t)(xb0 + 16*j) * Kc + ct * KC + xq));
                };
                auto stsX = [&](int buf) {
                    float* sx = s_xa + buf * Bv * XST;
                    #pragma unroll
                    for (int j = 0; j < 4; ++j)
                        *(float4*)(sx + (xb0 + 16*j) * XST + xq) = xs[j];
                };
                auto cpwC = [&](int ct, int buf) {
                    float* sw = s_wa + buf * 21 * KC;
                    for (int i = tid; i < NR * 32; i += NTHR) {
                        int r = i >> 5, q = (i & 31) * 4;
                        int grow = (r & 1) * Sv + s0 + (r >> 1);
                        cpacg(sw + r * KC + q, W2 + (size_t)grow * Kc + ct * KC + q);
                    }
                };

                ldxC(0); stsX(0); cpwC(0, 0); CPCOMMIT();
                for (int ct = 0; ct < NCH; ++ct) {
                    const int buf = ct & 1;
                    if (ct + 1 < NCH) { ldxC(ct + 1); cpwC(ct + 1, buf ^ 1); CPCOMMIT(); CPWAIT1(); }
                    else CPWAIT0();
                    __syncthreads();
                    const float* sw = s_wa + buf * 21 * KC;
                    const float* xr = s_xa + buf * Bv * XST + b * XST;
                    const int kb = seg * 16;
                    if (isPr) {
                        #pragma unroll
                        for (int kk = 0; kk < 16; kk += 4) {
                            float4 x4 = *(const float4*)(xr + kb + kk);
                            #pragma unroll
                            for (int r = 0; r < 8; ++r) fma4(aC[r], x4, sw + r*KC + kb + kk);
                        }
                    } else {
                        #pragma unroll
                        for (int kk = 0; kk < 16; kk += 4) {
                            float4 x4 = *(const float4*)(xr + kb + kk);
                            #pragma unroll
                            for (int r = 0; r < 4; ++r) fma4(aC[r], x4, sw + r*KC + kb + kk);
                        }
                    }
                    __syncthreads();
                    if (ct + 1 < NCH) stsX(buf ^ 1);
                }

                #pragma unroll
                for (int r = 0; r < 8; ++r)
                    if (r < NR) s_red[(r*64 + b)*RST + seg] = aC[r];
                __syncthreads();

                float v = 0.f; int rr = 0, bi = 0, s = 0, role = 0;
                const bool fin = (tid < NR * 64);
                if (fin) {
                    rr = tid >> 6; bi = tid & 63;
                    role = rr & 1; s = s0 + (rr >> 1);
                    float sum = 0.f;
                    #pragma unroll
                    for (int s2 = 0; s2 < 8; ++s2) sum += s_red[(rr*64 + bi)*RST + s2];
                    v = sum + __ldg(&B2[role * Sv + s]);
                    const size_t oidx = ((size_t)bi * Sv + s) * Tv + t;
                    if (isPr) {
                        if (role == 0) o_pm[oidx] = v;
                        else           o_ps[oidx] = sftp(v) + 1e-6f;
                    } else {
                        if (role == 1) {
                            float sd = sftp(v) + 1e-6f;
                            o_qs[oidx] = sd;
                            s_ex[(rr >> 1) * 64 + bi] = sd;
                        }
                    }
                }
                __syncthreads();
                if (isPo && fin && role == 0) {
                    float sd = s_ex[(rr >> 1) * 64 + bi];
                    float nz = __ldg(&noise[((size_t)bi * Tv + t) * Sv + s]);
                    float z  = v + sd * nz;                        // rsample
                    g_z[bi * Sv + s] = z * s_keep[bi];             // mask folded in
                    o_z[((size_t)bi * Tv + t) * Sv + s] = z;
                    o_qm[((size_t)bi * Sv + s) * Tv + t] = v;
                }
            }
        }
        gridbar();
    }
}

extern "C" void kernel_launch(void* const* d_in, const int* in_sizes, int n_in,
                              void* d_out, int out_size) {
    (void)in_sizes; (void)n_in; (void)out_size;
    cudaFuncSetAttribute(rssm_kernel, cudaFuncAttributeMaxDynamicSharedMemorySize, SMEM_BYTES);
    rssm_kernel<<<NBLK, NTHR, SMEM_BYTES>>>(
        (const float*)d_in[0],          // obs
        (const float*)d_in[1],          // action
        (const unsigned char*)d_in[2],  // resets
        (const float*)d_in[3],          // noise
        (const float*)d_in[4],          // w_ih
        (const float*)d_in[5],          // w_hh
        (const float*)d_in[6],          // b_ih
        (const float*)d_in[7],          // b_hh
        (const float*)d_in[8],          // pr_w1
        (const float*)d_in[9],          // pr_b1
        (const float*)d_in[10],         // pr_w2
        (const float*)d_in[11],         // pr_b2
        (const float*)d_in[12],         // po_w1
        (const float*)d_in[13],         // po_b1
        (const float*)d_in[14],         // po_w2
        (const float*)d_in[15],         // po_b2
        (float*)d_out);
}

// round 15
// speedup vs baseline: 3.8766x; 1.1158x over previous
#include <cuda_runtime.h>
#include <math.h>

#define Bv   64
#define Tv   256
#define Hv   1024
#define Sv   128
#define OBSv 1024
#define ACTv 32
#define NBLK 148
#define NTHR 512
#define KC   128
#define XST  132
#define RST  17      // 16 segs + 1 pad (odd -> conflict-free)

__device__ __align__(16) float g_h[2][Bv * Hv];
__device__ __align__(16) float g_z[Bv * Sv];
__device__ __align__(16) float g_a1[Bv * 512];
__device__ __align__(16) float g_a2[Bv * 1024];
__device__ unsigned int g_barc;
__device__ volatile unsigned int g_barg;

__device__ __forceinline__ void fma44(float& a0, float& a1, float4 xA, float4 xB, const float* wp) {
    float4 w = *(const float4*)wp;
    a0 = fmaf(xA.x, w.x, a0); a0 = fmaf(xA.y, w.y, a0);
    a0 = fmaf(xA.z, w.z, a0); a0 = fmaf(xA.w, w.w, a0);
    a1 = fmaf(xB.x, w.x, a1); a1 = fmaf(xB.y, w.y, a1);
    a1 = fmaf(xB.z, w.z, a1); a1 = fmaf(xB.w, w.w, a1);
}
__device__ __forceinline__ float sigm(float x) { return 1.f / (1.f + expf(-x)); }
__device__ __forceinline__ float sftp(float x) { return (x > 20.f) ? x : log1pf(expf(x)); }

__device__ __forceinline__ void cpacg(float* dst, const float* src) {
    unsigned int d = (unsigned int)__cvta_generic_to_shared(dst);
    asm volatile("cp.async.cg.shared.global [%0], [%1], 16;" :: "r"(d), "l"(src));
}
#define CPCOMMIT() asm volatile("cp.async.commit_group;")
#define CPWAIT1()  asm volatile("cp.async.wait_group 1;")
#define CPWAIT0()  asm volatile("cp.async.wait_group 0;")

__device__ __forceinline__ void gridbar() {
    __threadfence();
    __syncthreads();
    if (threadIdx.x == 0) {
        unsigned int my = g_barg;
        if (atomicAdd(&g_barc, 1u) == NBLK - 1u) {
            g_barc = 0u; __threadfence(); g_barg = my + 1u;
        } else {
            while (g_barg == my) __nanosleep(64);
            __threadfence();
        }
    }
    __syncthreads();
}

// smem floats: xa 16896 | wa 5376 | nx 7616 | keep 64 | ex 128
#define OFF_WA 16896
#define OFF_NX 22272
#define OFF_KP 29888
#define OFF_EX 29952
#define SMEM_BYTES (30080 * 4)

__global__ void __launch_bounds__(NTHR, 1)
rssm_kernel(const float* __restrict__ obs, const float* __restrict__ action,
            const unsigned char* __restrict__ resets, const float* __restrict__ noise,
            const float* __restrict__ w_ih, const float* __restrict__ w_hh,
            const float* __restrict__ b_ih, const float* __restrict__ b_hh,
            const float* __restrict__ pw1, const float* __restrict__ pb1,
            const float* __restrict__ pw2, const float* __restrict__ pb2,
            const float* __restrict__ qw1, const float* __restrict__ qb1,
            const float* __restrict__ qw2, const float* __restrict__ qb2,
            float* __restrict__ out)
{
    extern __shared__ __align__(16) float sm[];
    float* s_xa   = sm;
    float* s_wa   = sm + OFF_WA;
    float* s_nx   = sm + OFF_NX;
    float* s_keep = sm + OFF_KP;
    float* s_ex   = sm + OFF_EX;
    float* s_red  = s_xa;                       // aliases x bufs (max 15232 fl)

    const int tid = threadIdx.x, bid = blockIdx.x;
    const int bl = tid & 31, sg = tid >> 5;     // 32 lanes x 2 batches, 16 K-segs
    const int xb0 = tid >> 5;                   // staging rows (+16j)
    const int xq  = (tid & 31) * 4;
    const int ab  = tid >> 3;                   // action staging
    const int aq  = (tid & 7) * 4;

    float* o_pm = out;
    float* o_ps = out + (size_t)1 * Bv * Sv * Tv;
    float* o_qm = out + (size_t)2 * Bv * Sv * Tv;
    float* o_qs = out + (size_t)3 * Bv * Sv * Tv;
    float* o_h  = out + (size_t)4 * Bv * Sv * Tv;
    float* o_z  = o_h + (size_t)Bv * Tv * Hv;

    for (int i = bid * NTHR + tid; i < Bv * Hv; i += NBLK * NTHR) g_h[0][i] = 0.f;
    for (int i = bid * NTHR + tid; i < Bv * Sv; i += NBLK * NTHR) g_z[i] = 0.f;
    if (tid < Bv) s_keep[tid] = resets[tid] ? 0.f : 1.f;
    gridbar();

    float4 xs[4];

    for (int t = 0; t < Tv; ++t) {
        const float* hp = g_h[t & 1];
        float* hc = g_h[(t + 1) & 1];

        // ============ Phase A: GRU gates, 2 batches/thread =================
        if (bid < 147) {
            const int c0 = bid * 7;
            float aR0[7], aR1[7], aU0[7], aU1[7], aN0[7], aN1[7];
            #pragma unroll
            for (int u = 0; u < 7; ++u) { aR0[u]=aR1[u]=aU0[u]=aU1[u]=aN0[u]=aN1[u]=0.f; }

            auto ldxA = [&](int ct) {
                if (ct == 0) {
                    #pragma unroll
                    for (int j = 0; j < 4; ++j)
                        xs[j] = __ldcg((const float4*)(g_z + (xb0 + 16*j) * Sv + xq));
                } else if (ct == 1) {
                    if (t > 0) xs[0] = __ldcg((const float4*)(action + ((size_t)ab * Tv + (t-1)) * ACTv + aq));
                    else       xs[0] = make_float4(0.f, 0.f, 0.f, 0.f);
                } else {
                    #pragma unroll
                    for (int j = 0; j < 4; ++j)
                        xs[j] = __ldcg((const float4*)(hp + (size_t)(xb0 + 16*j) * Hv + (ct-2) * KC + xq));
                }
            };
            auto stsA = [&](int ct, int buf) {
                float* sx = s_xa + buf * Bv * XST;
                if (ct == 1) *(float4*)(sx + ab * XST + aq) = xs[0];
                else {
                    #pragma unroll
                    for (int j = 0; j < 4; ++j)
                        *(float4*)(sx + (xb0 + 16*j) * XST + xq) = xs[j];
                }
            };
            auto cpwA = [&](int ct, int buf) {
                float* sw = s_wa + buf * 21 * KC;
                if (ct == 1) {
                    for (int i = tid; i < 21 * 8; i += NTHR) {
                        int r = i >> 3, q = (i & 7) * 4;
                        int g = r / 7, uu = r - g * 7;
                        int grow = g * Hv + min(c0 + uu, Hv - 1);
                        cpacg(sw + r * KC + q, w_ih + (size_t)grow * 160 + 128 + q);
                    }
                } else {
                    for (int i = tid; i < 21 * 32; i += NTHR) {
                        int r = i >> 5, q = (i & 31) * 4;
                        int g = r / 7, uu = r - g * 7;
                        int grow = g * Hv + min(c0 + uu, Hv - 1);
                        const float* src = (ct == 0)
                            ? w_ih + (size_t)grow * 160 + q
                            : w_hh + (size_t)grow * Hv + (ct-2) * KC + q;
                        cpacg(sw + r * KC + q, src);
                    }
                }
            };

            ldxA(0); stsA(0, 0); cpwA(0, 0); CPCOMMIT();
            for (int ct = 0; ct < 10; ++ct) {
                const int buf = ct & 1;
                if (ct + 1 < 10) { ldxA(ct + 1); cpwA(ct + 1, buf ^ 1); CPCOMMIT(); CPWAIT1(); }
                else CPWAIT0();
                __syncthreads();
                const float* sw = s_wa + buf * 21 * KC;
                const float* x0 = s_xa + buf * Bv * XST + bl * XST;
                const float* x1 = x0 + 32 * XST;
                if (ct == 1) {
                    const int kb = sg * 2;
                    float2 xA = *(const float2*)(x0 + kb), xB = *(const float2*)(x1 + kb);
                    #pragma unroll
                    for (int u = 0; u < 7; ++u) {
                        float2 w;
                        w = *(const float2*)(sw + u*KC + kb);
                        aR0[u] = fmaf(xA.x, w.x, fmaf(xA.y, w.y, aR0[u]));
                        aR1[u] = fmaf(xB.x, w.x, fmaf(xB.y, w.y, aR1[u]));
                        w = *(const float2*)(sw + (7+u)*KC + kb);
                        aU0[u] = fmaf(xA.x, w.x, fmaf(xA.y, w.y, aU0[u]));
                        aU1[u] = fmaf(xB.x, w.x, fmaf(xB.y, w.y, aU1[u]));
                        w = *(const float2*)(sw + (14+u)*KC + kb);
                        aN0[u] = fmaf(xA.x, w.x, fmaf(xA.y, w.y, aN0[u]));
                        aN1[u] = fmaf(xB.x, w.x, fmaf(xB.y, w.y, aN1[u]));
                    }
                } else {
                    const int kb = sg * 8;
                    #pragma unroll
                    for (int kk = 0; kk < 8; kk += 4) {
                        float4 xA = *(const float4*)(x0 + kb + kk);
                        float4 xB = *(const float4*)(x1 + kb + kk);
                        #pragma unroll
                        for (int u = 0; u < 7; ++u) {
                            fma44(aR0[u], aR1[u], xA, xB, sw + u*KC + kb + kk);
                            fma44(aU0[u], aU1[u], xA, xB, sw + (7+u)*KC + kb + kk);
                            fma44(aN0[u], aN1[u], xA, xB, sw + (14+u)*KC + kb + kk);
                        }
                    }
                }
                if (ct == 1) {      // retire n-gate x-side partials; reuse regs for h-side
                    #pragma unroll
                    for (int u = 0; u < 7; ++u) {
                        s_nx[(u*64 + bl)      * RST + sg] = aN0[u];
                        s_nx[(u*64 + bl + 32) * RST + sg] = aN1[u];
                        aN0[u] = 0.f; aN1[u] = 0.f;
                    }
                }
                __syncthreads();
                if (ct + 1 < 10) stsA(ct + 1, buf ^ 1);
            }

            // pass 1: reduce R,U (14 rows)
            #pragma unroll
            for (int u = 0; u < 7; ++u) {
                s_red[(u*64 + bl)       * RST + sg] = aR0[u];
                s_red[(u*64 + bl + 32)  * RST + sg] = aR1[u];
                s_red[((7+u)*64 + bl)      * RST + sg] = aU0[u];
                s_red[((7+u)*64 + bl + 32) * RST + sg] = aU1[u];
            }
            __syncthreads();
            float sR = 0.f, sU = 0.f;
            if (tid < 448) {
                const int u = tid >> 6, bi = tid & 63;
                #pragma unroll
                for (int s2 = 0; s2 < 16; ++s2) {
                    sR += s_red[(u*64 + bi) * RST + s2];
                    sU += s_red[((7+u)*64 + bi) * RST + s2];
                }
            }
            __syncthreads();
            // pass 2: reduce NH (7 rows)
            #pragma unroll
            for (int u = 0; u < 7; ++u) {
                s_red[(u*64 + bl)      * RST + sg] = aN0[u];
                s_red[(u*64 + bl + 32) * RST + sg] = aN1[u];
            }
            __syncthreads();
            if (tid < 448) {
                const int u = tid >> 6, bi = tid & 63;
                const int j = c0 + u;
                if (j < Hv) {
                    float sH = 0.f, sX = 0.f;
                    #pragma unroll
                    for (int s2 = 0; s2 < 16; ++s2) {
                        sH += s_red[(u*64 + bi) * RST + s2];
                        sX += s_nx[(u*64 + bi) * RST + s2];
                    }
                    const float km = s_keep[bi];
                    const float hm = __ldcg(&hp[bi * Hv + j]);
                    float r  = sigm(sR + __ldg(&b_ih[j])       + __ldg(&b_hh[j]));
                    float uu = sigm(sU + __ldg(&b_ih[Hv+j])    + __ldg(&b_hh[Hv+j]));
                    float n  = tanhf(sX + __ldg(&b_ih[2*Hv+j]) + r * (sH + __ldg(&b_hh[2*Hv+j])));
                    float hn = (1.f - uu) * n + uu * hm;
                    hc[bi * Hv + j] = hn * km;
                    o_h[((size_t)bi * Tv + t) * Hv + j] = hn;
                }
            }
        }
        gridbar();

        // ====== Phase B: posterior L1 (K=2048) + fused prior L1 ============
        if (bid < 147) {
            const int c0q = bid * 7, c0p = bid * 4;
            const bool hasP = (bid < 128);
            float aQ0[7], aQ1[7], aP0[4], aP1[4];
            #pragma unroll
            for (int r = 0; r < 7; ++r) { aQ0[r]=aQ1[r]=0.f; }
            #pragma unroll
            for (int r = 0; r < 4; ++r) { aP0[r]=aP1[r]=0.f; }

            auto ldxB = [&](int ct) {
                #pragma unroll
                for (int j = 0; j < 4; ++j)
                    xs[j] = (ct < 8)
                        ? __ldcg((const float4*)(hc + (size_t)(xb0 + 16*j) * Hv + ct * KC + xq))
                        : __ldcg((const float4*)(obs + ((size_t)(xb0 + 16*j) * Tv + t) * OBSv + (ct-8) * KC + xq));
            };
            auto stsX = [&](int buf) {
                float* sx = s_xa + buf * Bv * XST;
                #pragma unroll
                for (int j = 0; j < 4; ++j)
                    *(float4*)(sx + (xb0 + 16*j) * XST + xq) = xs[j];
            };
            auto cpwB = [&](int ct, int buf) {
                float* sw = s_wa + buf * 21 * KC;
                for (int i = tid; i < 11 * 32; i += NTHR) {
                    int r = i >> 5, q = (i & 31) * 4;
                    if (r < 7)
                        cpacg(sw + r * KC + q, qw1 + (size_t)min(c0q + r, 1023) * 2048 + ct * KC + q);
                    else if (hasP && ct < 8)
                        cpacg(sw + r * KC + q, pw1 + (size_t)(c0p + r - 7) * Hv + ct * KC + q);
                }
            };

            ldxB(0); stsX(0); cpwB(0, 0); CPCOMMIT();
            for (int ct = 0; ct < 16; ++ct) {
                const int buf = ct & 1;
                if (ct + 1 < 16) { ldxB(ct + 1); cpwB(ct + 1, buf ^ 1); CPCOMMIT(); CPWAIT1(); }
                else CPWAIT0();
                __syncthreads();
                const float* sw = s_wa + buf * 21 * KC;
                const float* x0 = s_xa + buf * Bv * XST + bl * XST;
                const float* x1 = x0 + 32 * XST;
                const int kb = sg * 8;
                #pragma unroll
                for (int kk = 0; kk < 8; kk += 4) {
                    float4 xA = *(const float4*)(x0 + kb + kk);
                    float4 xB = *(const float4*)(x1 + kb + kk);
                    #pragma unroll
                    for (int r = 0; r < 7; ++r) fma44(aQ0[r], aQ1[r], xA, xB, sw + r*KC + kb + kk);
                    if (hasP && ct < 8) {
                        #pragma unroll
                        for (int r = 0; r < 4; ++r) fma44(aP0[r], aP1[r], xA, xB, sw + (7+r)*KC + kb + kk);
                    }
                }
                __syncthreads();
                if (ct + 1 < 16) stsX(buf ^ 1);
            }

            #pragma unroll
            for (int r = 0; r < 7; ++r) {
                s_red[(r*64 + bl)      * RST + sg] = aQ0[r];
                s_red[(r*64 + bl + 32) * RST + sg] = aQ1[r];
            }
            #pragma unroll
            for (int r = 0; r < 4; ++r) {
                s_red[((7+r)*64 + bl)      * RST + sg] = aP0[r];
                s_red[((7+r)*64 + bl + 32) * RST + sg] = aP1[r];
            }
            __syncthreads();
            for (int idx = tid; idx < 704; idx += NTHR) {
                const int r = idx >> 6, bi = idx & 63;
                float sum = 0.f;
                #pragma unroll
                for (int s2 = 0; s2 < 16; ++s2) sum += s_red[(r*64 + bi) * RST + s2];
                if (r < 7) {
                    int col = c0q + r;
                    if (col < 1024) g_a2[bi * 1024 + col] = fmaxf(sum + __ldg(&qb1[col]), 0.f);
                } else if (hasP) {
                    int col = c0p + (r - 7);
                    g_a1[bi * 512 + col] = fmaxf(sum + __ldg(&pb1[col]), 0.f);
                }
            }
        }
        gridbar();

        // ====== Phase C: heads. blocks 0..31 prior, 32..95 posterior =======
        {
            const bool isPr = (bid < 32);
            const bool isPo = (bid >= 32 && bid < 96);
            if (isPr || isPo) {
                const int NR  = isPr ? 8 : 4;
                const int NCH = isPr ? 4 : 8;
                const int s0  = isPr ? bid * 4 : (bid - 32) * 2;
                const int Kc  = isPr ? 512 : 1024;
                const float* W2 = isPr ? pw2 : qw2;
                const float* B2 = isPr ? pb2 : qb2;
                const float* Ain = isPr ? g_a1 : g_a2;
                float aC0[8], aC1[8];
                #pragma unroll
                for (int r = 0; r < 8; ++r) { aC0[r]=aC1[r]=0.f; }

                auto ldxC = [&](int ct) {
                    #pragma unroll
                    for (int j = 0; j < 4; ++j)
                        xs[j] = __ldcg((const float4*)(Ain + (size_t)(xb0 + 16*j) * Kc + ct * KC + xq));
                };
                auto stsX = [&](int buf) {
                    float* sx = s_xa + buf * Bv * XST;
                    #pragma unroll
                    for (int j = 0; j < 4; ++j)
                        *(float4*)(sx + (xb0 + 16*j) * XST + xq) = xs[j];
                };
                auto cpwC = [&](int ct, int buf) {
                    float* sw = s_wa + buf * 21 * KC;
                    for (int i = tid; i < NR * 32; i += NTHR) {
                        int r = i >> 5, q = (i & 31) * 4;
                        int grow = (r & 1) * Sv + s0 + (r >> 1);
                        cpacg(sw + r * KC + q, W2 + (size_t)grow * Kc + ct * KC + q);
                    }
                };

                ldxC(0); stsX(0); cpwC(0, 0); CPCOMMIT();
                for (int ct = 0; ct < NCH; ++ct) {
                    const int buf = ct & 1;
                    if (ct + 1 < NCH) { ldxC(ct + 1); cpwC(ct + 1, buf ^ 1); CPCOMMIT(); CPWAIT1(); }
                    else CPWAIT0();
                    __syncthreads();
                    const float* sw = s_wa + buf * 21 * KC;
                    const float* x0 = s_xa + buf * Bv * XST + bl * XST;
                    const float* x1 = x0 + 32 * XST;
                    const int kb = sg * 8;
                    #pragma unroll
                    for (int kk = 0; kk < 8; kk += 4) {
                        float4 xA = *(const float4*)(x0 + kb + kk);
                        float4 xB = *(const float4*)(x1 + kb + kk);
                        if (isPr) {
                            #pragma unroll
                            for (int r = 0; r < 8; ++r) fma44(aC0[r], aC1[r], xA, xB, sw + r*KC + kb + kk);
                        } else {
                            #pragma unroll
                            for (int r = 0; r < 4; ++r) fma44(aC0[r], aC1[r], xA, xB, sw + r*KC + kb + kk);
                        }
                    }
                    __syncthreads();
                    if (ct + 1 < NCH) stsX(buf ^ 1);
                }

                #pragma unroll
                for (int r = 0; r < 8; ++r) {
                    if (r < NR) {
                        s_red[(r*64 + bl)      * RST + sg] = aC0[r];
                        s_red[(r*64 + bl + 32) * RST + sg] = aC1[r];
                    }
                }
                __syncthreads();

                float v = 0.f; int rr = 0, bi = 0, s = 0, role = 0;
                const bool fin = (tid < NR * 64);
                if (fin) {
                    rr = tid >> 6; bi = tid & 63;
                    role = rr & 1; s = s0 + (rr >> 1);
                    float sum = 0.f;
                    #pragma unroll
                    for (int s2 = 0; s2 < 16; ++s2) sum += s_red[(rr*64 + bi) * RST + s2];
                    v = sum + __ldg(&B2[role * Sv + s]);
                    const size_t oidx = ((size_t)bi * Sv + s) * Tv + t;
                    if (isPr) {
                        if (role == 0) o_pm[oidx] = v;
                        else           o_ps[oidx] = sftp(v) + 1e-6f;
                    } else if (role == 1) {
                        float sd = sftp(v) + 1e-6f;
                        o_qs[oidx] = sd;
                        s_ex[(rr >> 1) * 64 + bi] = sd;
                    }
                }
                __syncthreads();
                if (isPo && fin && role == 0) {
                    float sd = s_ex[(rr >> 1) * 64 + bi];
                    float nz = __ldg(&noise[((size_t)bi * Tv + t) * Sv + s]);
                    float z  = v + sd * nz;
                    g_z[bi * Sv + s] = z * s_keep[bi];
                    o_z[((size_t)bi * Tv + t) * Sv + s] = z;
                    o_qm[((size_t)bi * Sv + s) * Tv + t] = v;
                }
            }
        }
        gridbar();
    }
}

extern "C" void kernel_launch(void* const* d_in, const int* in_sizes, int n_in,
                              void* d_out, int out_size) {
    (void)in_sizes; (void)n_in; (void)out_size;
    cudaFuncSetAttribute(rssm_kernel, cudaFuncAttributeMaxDynamicSharedMemorySize, SMEM_BYTES);
    rssm_kernel<<<NBLK, NTHR, SMEM_BYTES>>>(
        (const float*)d_in[0],  (const float*)d_in[1],
        (const unsigned char*)d_in[2], (const float*)d_in[3],
        (const float*)d_in[4],  (const float*)d_in[5],
        (const float*)d_in[6],  (const float*)d_in[7],
        (const float*)d_in[8],  (const float*)d_in[9],
        (const float*)d_in[10], (const float*)d_in[11],
        (const float*)d_in[12], (const float*)d_in[13],
        (const float*)d_in[14], (const float*)d_in[15],
        (float*)d_out);
}

// round 16
// speedup vs baseline: 4.0137x; 1.0354x over previous
#include <cuda_runtime.h>
#include <math.h>

#define Bv   64
#define Tv   256
#define Hv   1024
#define Sv   128
#define OBSv 1024
#define ACTv 32
#define NBLK 148
#define NTHR 512
#define KC   128
#define XST  132
#define RST  17
typedef unsigned long long ull;

__device__ __align__(16) float g_h[2][Bv * Hv];
__device__ __align__(16) float g_z[Bv * Sv];
__device__ __align__(16) float g_a1[Bv * 512];
__device__ __align__(16) float g_a2[Bv * 1024];
__device__ unsigned int g_barc;
__device__ volatile unsigned int g_barg;

__device__ __forceinline__ void fma44(float& a0, float& a1, float4 xA, float4 xB, const float* wp) {
    float4 w = *(const float4*)wp;
    a0 = fmaf(xA.x, w.x, a0); a0 = fmaf(xA.y, w.y, a0);
    a0 = fmaf(xA.z, w.z, a0); a0 = fmaf(xA.w, w.w, a0);
    a1 = fmaf(xB.x, w.x, a1); a1 = fmaf(xB.y, w.y, a1);
    a1 = fmaf(xB.z, w.z, a1); a1 = fmaf(xB.w, w.w, a1);
}
__device__ __forceinline__ void ffma2(ull& a, ull x, ull w) {
    asm("fma.rn.f32x2 %0, %1, %2, %0;" : "+l"(a) : "l"(x), "l"(w));
}
__device__ __forceinline__ float foldu(ull a) {
    float x, y; asm("mov.b64 {%0, %1}, %2;" : "=f"(x), "=f"(y) : "l"(a));
    return x + y;
}
__device__ __forceinline__ float sigm(float x) { return 1.f / (1.f + expf(-x)); }
__device__ __forceinline__ float sftp(float x) { return (x > 20.f) ? x : log1pf(expf(x)); }

// cp.async.cg: L2 path (L1-bypass) -> coherent for device-written data too
__device__ __forceinline__ void cpacg(float* dst, const float* src) {
    unsigned int d = (unsigned int)__cvta_generic_to_shared(dst);
    asm volatile("cp.async.cg.shared.global [%0], [%1], 16;" :: "r"(d), "l"(src));
}
#define CPCOMMIT() asm volatile("cp.async.commit_group;")
#define CPWAIT1()  asm volatile("cp.async.wait_group 1;")

__device__ __forceinline__ void gridbar() {
    __threadfence();
    __syncthreads();
    if (threadIdx.x == 0) {
        unsigned int my = g_barg;
        if (atomicAdd(&g_barc, 1u) == NBLK - 1u) {
            g_barc = 0u; __threadfence(); g_barg = my + 1u;
        } else {
            while (g_barg == my) __nanosleep(64);
            __threadfence();
        }
    }
    __syncthreads();
}

// smem floats: 3 stages x (x 8448 + w 2688) = 33408 | nx 7616 | keep 64 | ex 128
#define STGF   11136
#define OFF_NX 33408
#define OFF_KP 41024
#define OFF_EX 41088
#define SMEM_BYTES (41216 * 4)

__global__ void __launch_bounds__(NTHR, 1)
rssm_kernel(const float* __restrict__ obs, const float* __restrict__ action,
            const unsigned char* __restrict__ resets, const float* __restrict__ noise,
            const float* __restrict__ w_ih, const float* __restrict__ w_hh,
            const float* __restrict__ b_ih, const float* __restrict__ b_hh,
            const float* __restrict__ pw1, const float* __restrict__ pb1,
            const float* __restrict__ pw2, const float* __restrict__ pb2,
            const float* __restrict__ qw1, const float* __restrict__ qb1,
            const float* __restrict__ qw2, const float* __restrict__ qb2,
            float* __restrict__ out)
{
    extern __shared__ __align__(16) float sm[];
    float* s_nx   = sm + OFF_NX;
    float* s_keep = sm + OFF_KP;
    float* s_ex   = sm + OFF_EX;
    float* s_red  = sm;                         // aliases stages 0,1 (22272 fl)

    const int tid = threadIdx.x, bid = blockIdx.x;
    const int bl = tid & 31, sg = tid >> 5;     // 32 lanes x 2 batches, 16 K-segs
    const int xb0 = tid >> 5;                   // x staging rows (+16j)
    const int xq  = (tid & 31) * 4;
    const int ab  = tid >> 3;                   // action staging
    const int aq  = (tid & 7) * 4;

    float* o_pm = out;
    float* o_ps = out + (size_t)1 * Bv * Sv * Tv;
    float* o_qm = out + (size_t)2 * Bv * Sv * Tv;
    float* o_qs = out + (size_t)3 * Bv * Sv * Tv;
    float* o_h  = out + (size_t)4 * Bv * Sv * Tv;
    float* o_z  = o_h + (size_t)Bv * Tv * Hv;

    for (int i = bid * NTHR + tid; i < Bv * Hv; i += NBLK * NTHR) g_h[0][i] = 0.f;
    for (int i = bid * NTHR + tid; i < Bv * Sv; i += NBLK * NTHR) g_z[i] = 0.f;
    if (tid < Bv) s_keep[tid] = resets[tid] ? 0.f : 1.f;
    gridbar();

    for (int t = 0; t < Tv; ++t) {
        const float* hp = g_h[t & 1];
        float* hc = g_h[(t + 1) & 1];

        // ============ Phase A: GRU gates (scalar FFMA, async-staged) =======
        if (bid < 147) {
            const int c0 = bid * 7;
            float aR0[7], aR1[7], aU0[7], aU1[7], aN0[7], aN1[7];
            #pragma unroll
            for (int u = 0; u < 7; ++u) { aR0[u]=aR1[u]=aU0[u]=aU1[u]=aN0[u]=aN1[u]=0.f; }

            auto stageA = [&](int ct, int stg) {
                float* sx = sm + stg * STGF;
                float* sw = sx + 8448;
                if (ct == 0) {
                    #pragma unroll
                    for (int j = 0; j < 4; ++j) {
                        int row = xb0 + 16 * j;
                        cpacg(sx + row * XST + xq, g_z + row * Sv + xq);
                    }
                } else if (ct == 1) {
                    if (t > 0) cpacg(sx + ab * XST + aq,
                                     action + ((size_t)ab * Tv + (t-1)) * ACTv + aq);
                    else *(float4*)(sx + ab * XST + aq) = make_float4(0.f,0.f,0.f,0.f);
                } else {
                    #pragma unroll
                    for (int j = 0; j < 4; ++j) {
                        int row = xb0 + 16 * j;
                        cpacg(sx + row * XST + xq, hp + (size_t)row * Hv + (ct-2) * KC + xq);
                    }
                }
                if (ct == 1) {
                    for (int i = tid; i < 21 * 8; i += NTHR) {
                        int r = i >> 3, q = (i & 7) * 4;
                        int g = r / 7, uu = r - g * 7;
                        int grow = g * Hv + min(c0 + uu, Hv - 1);
                        cpacg(sw + r * KC + q, w_ih + (size_t)grow * 160 + 128 + q);
                    }
                } else {
                    for (int i = tid; i < 21 * 32; i += NTHR) {
                        int r = i >> 5, q = (i & 31) * 4;
                        int g = r / 7, uu = r - g * 7;
                        int grow = g * Hv + min(c0 + uu, Hv - 1);
                        const float* src = (ct == 0)
                            ? w_ih + (size_t)grow * 160 + q
                            : w_hh + (size_t)grow * Hv + (ct-2) * KC + q;
                        cpacg(sw + r * KC + q, src);
                    }
                }
            };

            stageA(0, 0); CPCOMMIT(); stageA(1, 1); CPCOMMIT();
            for (int ct = 0; ct < 10; ++ct) {
                const int stg = ct % 3;
                CPWAIT1();
                __syncthreads();
                const float* sx = sm + stg * STGF;
                const float* sw = sx + 8448;
                const float* x0 = sx + bl * XST;
                const float* x1 = x0 + 32 * XST;
                if (ct == 1) {
                    const int kb = sg * 2;
                    float2 xA = *(const float2*)(x0 + kb), xB = *(const float2*)(x1 + kb);
                    #pragma unroll
                    for (int u = 0; u < 7; ++u) {
                        float2 w;
                        w = *(const float2*)(sw + u*KC + kb);
                        aR0[u] = fmaf(xA.x, w.x, fmaf(xA.y, w.y, aR0[u]));
                        aR1[u] = fmaf(xB.x, w.x, fmaf(xB.y, w.y, aR1[u]));
                        w = *(const float2*)(sw + (7+u)*KC + kb);
                        aU0[u] = fmaf(xA.x, w.x, fmaf(xA.y, w.y, aU0[u]));
                        aU1[u] = fmaf(xB.x, w.x, fmaf(xB.y, w.y, aU1[u]));
                        w = *(const float2*)(sw + (14+u)*KC + kb);
                        aN0[u] = fmaf(xA.x, w.x, fmaf(xA.y, w.y, aN0[u]));
                        aN1[u] = fmaf(xB.x, w.x, fmaf(xB.y, w.y, aN1[u]));
                    }
                } else {
                    const int kb = sg * 8;
                    #pragma unroll
                    for (int kk = 0; kk < 8; kk += 4) {
                        float4 xA = *(const float4*)(x0 + kb + kk);
                        float4 xB = *(const float4*)(x1 + kb + kk);
                        #pragma unroll
                        for (int u = 0; u < 7; ++u) {
                            fma44(aR0[u], aR1[u], xA, xB, sw + u*KC + kb + kk);
                            fma44(aU0[u], aU1[u], xA, xB, sw + (7+u)*KC + kb + kk);
                            fma44(aN0[u], aN1[u], xA, xB, sw + (14+u)*KC + kb + kk);
                        }
                    }
                }
                if (ct == 1) {      // retire n-gate x-side partials
                    #pragma unroll
                    for (int u = 0; u < 7; ++u) {
                        s_nx[(u*64 + bl)      * RST + sg] = aN0[u];
                        s_nx[(u*64 + bl + 32) * RST + sg] = aN1[u];
                        aN0[u] = 0.f; aN1[u] = 0.f;
                    }
                }
                if (ct + 2 < 10) stageA(ct + 2, (ct + 2) % 3);
                CPCOMMIT();
            }
            __syncthreads();

            // pass 1: reduce R,U
            #pragma unroll
            for (int u = 0; u < 7; ++u) {
                s_red[(u*64 + bl)          * RST + sg] = aR0[u];
                s_red[(u*64 + bl + 32)     * RST + sg] = aR1[u];
                s_red[((7+u)*64 + bl)      * RST + sg] = aU0[u];
                s_red[((7+u)*64 + bl + 32) * RST + sg] = aU1[u];
            }
            __syncthreads();
            float sR = 0.f, sU = 0.f;
            if (tid < 448) {
                const int u = tid >> 6, bi = tid & 63;
                #pragma unroll
                for (int s2 = 0; s2 < 16; ++s2) {
                    sR += s_red[(u*64 + bi) * RST + s2];
                    sU += s_red[((7+u)*64 + bi) * RST + s2];
                }
            }
            __syncthreads();
            // pass 2: reduce NH + pointwise
            #pragma unroll
            for (int u = 0; u < 7; ++u) {
                s_red[(u*64 + bl)      * RST + sg] = aN0[u];
                s_red[(u*64 + bl + 32) * RST + sg] = aN1[u];
            }
            __syncthreads();
            if (tid < 448) {
                const int u = tid >> 6, bi = tid & 63;
                const int j = c0 + u;
                if (j < Hv) {
                    float sH = 0.f, sX = 0.f;
                    #pragma unroll
                    for (int s2 = 0; s2 < 16; ++s2) {
                        sH += s_red[(u*64 + bi) * RST + s2];
                        sX += s_nx[(u*64 + bi) * RST + s2];
                    }
                    const float km = s_keep[bi];
                    const float hm = __ldcg(&hp[bi * Hv + j]);
                    float r  = sigm(sR + __ldg(&b_ih[j])       + __ldg(&b_hh[j]));
                    float uu = sigm(sU + __ldg(&b_ih[Hv+j])    + __ldg(&b_hh[Hv+j]));
                    float n  = tanhf(sX + __ldg(&b_ih[2*Hv+j]) + r * (sH + __ldg(&b_hh[2*Hv+j])));
                    float hn = (1.f - uu) * n + uu * hm;
                    hc[bi * Hv + j] = hn * km;
                    o_h[((size_t)bi * Tv + t) * Hv + j] = hn;
                }
            }
        }
        gridbar();

        // ====== Phase B: posterior L1 + fused prior L1 (f32x2) =============
        if (bid < 147) {
            const int c0q = bid * 7, c0p = bid * 4;
            const bool hasP = (bid < 128);
            ull aQ0[7], aQ1[7], aP0[4], aP1[4];
            #pragma unroll
            for (int r = 0; r < 7; ++r) { aQ0[r]=aQ1[r]=0ull; }
            #pragma unroll
            for (int r = 0; r < 4; ++r) { aP0[r]=aP1[r]=0ull; }

            auto stageB = [&](int ct, int stg) {
                float* sx = sm + stg * STGF;
                float* sw = sx + 8448;
                #pragma unroll
                for (int j = 0; j < 4; ++j) {
                    int row = xb0 + 16 * j;
                    const float* src = (ct < 8)
                        ? hc + (size_t)row * Hv + ct * KC + xq
                        : obs + ((size_t)row * Tv + t) * OBSv + (ct-8) * KC + xq;
                    cpacg(sx + row * XST + xq, src);
                }
                for (int i = tid; i < 11 * 32; i += NTHR) {
                    int r = i >> 5, q = (i & 31) * 4;
                    if (r < 7)
                        cpacg(sw + r * KC + q, qw1 + (size_t)min(c0q + r, 1023) * 2048 + ct * KC + q);
                    else if (hasP && ct < 8)
                        cpacg(sw + r * KC + q, pw1 + (size_t)(c0p + r - 7) * Hv + ct * KC + q);
                }
            };

            stageB(0, 0); CPCOMMIT(); stageB(1, 1); CPCOMMIT();
            for (int ct = 0; ct < 16; ++ct) {
                const int stg = ct % 3;
                CPWAIT1();
                __syncthreads();
                const float* sx = sm + stg * STGF;
                const float* sw = sx + 8448;
                const float* x0 = sx + bl * XST;
                const float* x1 = x0 + 32 * XST;
                const int kb = sg * 8;
                #pragma unroll
                for (int kk = 0; kk < 8; kk += 4) {
                    ulonglong2 xA = *(const ulonglong2*)(x0 + kb + kk);
                    ulonglong2 xB = *(const ulonglong2*)(x1 + kb + kk);
                    #pragma unroll
                    for (int r = 0; r < 7; ++r) {
                        ulonglong2 w = *(const ulonglong2*)(sw + r*KC + kb + kk);
                        ffma2(aQ0[r], xA.x, w.x); ffma2(aQ0[r], xA.y, w.y);
                        ffma2(aQ1[r], xB.x, w.x); ffma2(aQ1[r], xB.y, w.y);
                    }
                    if (hasP && ct < 8) {
                        #pragma unroll
                        for (int r = 0; r < 4; ++r) {
                            ulonglong2 w = *(const ulonglong2*)(sw + (7+r)*KC + kb + kk);
                            ffma2(aP0[r], xA.x, w.x); ffma2(aP0[r], xA.y, w.y);
                            ffma2(aP1[r], xB.x, w.x); ffma2(aP1[r], xB.y, w.y);
                        }
                    }
                }
                if (ct + 2 < 16) stageB(ct + 2, (ct + 2) % 3);
                CPCOMMIT();
            }
            __syncthreads();

            #pragma unroll
            for (int r = 0; r < 7; ++r) {
                s_red[(r*64 + bl)      * RST + sg] = foldu(aQ0[r]);
                s_red[(r*64 + bl + 32) * RST + sg] = foldu(aQ1[r]);
            }
            #pragma unroll
            for (int r = 0; r < 4; ++r) {
                s_red[((7+r)*64 + bl)      * RST + sg] = foldu(aP0[r]);
                s_red[((7+r)*64 + bl + 32) * RST + sg] = foldu(aP1[r]);
            }
            __syncthreads();
            for (int idx = tid; idx < 704; idx += NTHR) {
                const int r = idx >> 6, bi = idx & 63;
                float sum = 0.f;
                #pragma unroll
                for (int s2 = 0; s2 < 16; ++s2) sum += s_red[(r*64 + bi) * RST + s2];
                if (r < 7) {
                    int col = c0q + r;
                    if (col < 1024) g_a2[bi * 1024 + col] = fmaxf(sum + __ldg(&qb1[col]), 0.f);
                } else if (hasP) {
                    int col = c0p + (r - 7);
                    g_a1[bi * 512 + col] = fmaxf(sum + __ldg(&pb1[col]), 0.f);
                }
            }
        }
        gridbar();

        // ====== Phase C: heads (f32x2). blocks 0..31 prior, 32..95 post ====
        {
            const bool isPr = (bid < 32);
            const bool isPo = (bid >= 32 && bid < 96);
            if (isPr || isPo) {
                const int NR  = isPr ? 8 : 4;
                const int NCH = isPr ? 4 : 8;
                const int s0  = isPr ? bid * 4 : (bid - 32) * 2;
                const int Kc  = isPr ? 512 : 1024;
                const float* W2 = isPr ? pw2 : qw2;
                const float* B2 = isPr ? pb2 : qb2;
                const float* Ain = isPr ? g_a1 : g_a2;
                ull aC0[8], aC1[8];
                #pragma unroll
                for (int r = 0; r < 8; ++r) { aC0[r]=aC1[r]=0ull; }

                auto stageC = [&](int ct, int stg) {
                    float* sx = sm + stg * STGF;
                    float* sw = sx + 8448;
                    #pragma unroll
                    for (int j = 0; j < 4; ++j) {
                        int row = xb0 + 16 * j;
                        cpacg(sx + row * XST + xq, Ain + (size_t)row * Kc + ct * KC + xq);
                    }
                    for (int i = tid; i < NR * 32; i += NTHR) {
                        int r = i >> 5, q = (i & 31) * 4;
                        int grow = (r & 1) * Sv + s0 + (r >> 1);
                        cpacg(sw + r * KC + q, W2 + (size_t)grow * Kc + ct * KC + q);
                    }
                };

                stageC(0, 0); CPCOMMIT(); stageC(1, 1); CPCOMMIT();
                for (int ct = 0; ct < NCH; ++ct) {
                    const int stg = ct % 3;
                    CPWAIT1();
                    __syncthreads();
                    const float* sx = sm + stg * STGF;
                    const float* sw = sx + 8448;
                    const float* x0 = sx + bl * XST;
                    const float* x1 = x0 + 32 * XST;
                    const int kb = sg * 8;
                    #pragma unroll
                    for (int kk = 0; kk < 8; kk += 4) {
                        ulonglong2 xA = *(const ulonglong2*)(x0 + kb + kk);
                        ulonglong2 xB = *(const ulonglong2*)(x1 + kb + kk);
                        if (isPr) {
                            #pragma unroll
                            for (int r = 0; r < 8; ++r) {
                                ulonglong2 w = *(const ulonglong2*)(sw + r*KC + kb + kk);
                                ffma2(aC0[r], xA.x, w.x); ffma2(aC0[r], xA.y, w.y);
                                ffma2(aC1[r], xB.x, w.x); ffma2(aC1[r], xB.y, w.y);
                            }
                        } else {
                            #pragma unroll
                            for (int r = 0; r < 4; ++r) {
                                ulonglong2 w = *(const ulonglong2*)(sw + r*KC + kb + kk);
                                ffma2(aC0[r], xA.x, w.x); ffma2(aC0[r], xA.y, w.y);
                                ffma2(aC1[r], xB.x, w.x); ffma2(aC1[r], xB.y, w.y);
                            }
                        }
                    }
                    if (ct + 2 < NCH) stageC(ct + 2, (ct + 2) % 3);
                    CPCOMMIT();
                }
                __syncthreads();

                #pragma unroll
                for (int r = 0; r < 8; ++r) {
                    if (r < NR) {
                        s_red[(r*64 + bl)      * RST + sg] = foldu(aC0[r]);
                        s_red[(r*64 + bl + 32) * RST + sg] = foldu(aC1[r]);
                    }
                }
                __syncthreads();

                float v = 0.f; int rr = 0, bi = 0, s = 0, role = 0;
                const bool fin = (tid < NR * 64);
                if (fin) {
                    rr = tid >> 6; bi = tid & 63;
                    role = rr & 1; s = s0 + (rr >> 1);
                    float sum = 0.f;
                    #pragma unroll
                    for (int s2 = 0; s2 < 16; ++s2) sum += s_red[(rr*64 + bi) * RST + s2];
                    v = sum + __ldg(&B2[role * Sv + s]);
                    const size_t oidx = ((size_t)bi * Sv + s) * Tv + t;
                    if (isPr) {
                        if (role == 0) o_pm[oidx] = v;
                        else           o_ps[oidx] = sftp(v) + 1e-6f;
                    } else if (role == 1) {
                        float sd = sftp(v) + 1e-6f;
                        o_qs[oidx] = sd;
                        s_ex[(rr >> 1) * 64 + bi] = sd;
                    }
                }
                __syncthreads();
                if (isPo && fin && role == 0) {
                    float sd = s_ex[(rr >> 1) * 64 + bi];
                    float nz = __ldg(&noise[((size_t)bi * Tv + t) * Sv + s]);
                    float z  = v + sd * nz;
                    g_z[bi * Sv + s] = z * s_keep[bi];
                    o_z[((size_t)bi * Tv + t) * Sv + s] = z;
                    o_qm[((size_t)bi * Sv + s) * Tv + t] = v;
                }
            }
        }
        gridbar();
    }
}

extern "C" void kernel_launch(void* const* d_in, const int* in_sizes, int n_in,
                              void* d_out, int out_size) {
    (void)in_sizes; (void)n_in; (void)out_size;
    cudaFuncSetAttribute(rssm_kernel, cudaFuncAttributeMaxDynamicSharedMemorySize, SMEM_BYTES);
    rssm_kernel<<<NBLK, NTHR, SMEM_BYTES>>>(
        (const float*)d_in[0],  (const float*)d_in[1],
        (const unsigned char*)d_in[2], (const float*)d_in[3],
        (const float*)d_in[4],  (const float*)d_in[5],
        (const float*)d_in[6],  (const float*)d_in[7],
        (const float*)d_in[8],  (const float*)d_in[9],
        (const float*)d_in[10], (const float*)d_in[11],
        (const float*)d_in[12], (const float*)d_in[13],
        (const float*)d_in[14], (const float*)d_in[15],
        (float*)d_out);
}